// round 14
// baseline (speedup 1.0000x reference)
#include <cuda_runtime.h>
#include <cuda_bf16.h>

#define HID 64
#define MAX_OBJ 100000
#define MAX_GRAPHS 256

typedef unsigned int u32;
typedef unsigned long long u64;
typedef unsigned short u16;

__device__ float g_obj[MAX_OBJ * HID];
__device__ float g_agg[MAX_OBJ * HID];
__device__ int   g_deg[6 * MAX_OBJ];
__device__ float g_const[64 + 128 + 192];
__device__ float g_pooled[MAX_GRAPHS * HID];

// pre-split bf16 planes of g_obj: row = 32 u32 = 8 uint4 (64 values)
__device__ __align__(16) u32 g_objh[MAX_OBJ * 32];
__device__ __align__(16) u32 g_objl[MAX_OBJ * 32];

// pre-transposed, bf16-split weights, layout [N][K+8] u16 per half.
__device__ __align__(16) u16 g_wbuf[293888];

// ---------------------------------------------------------------------------
struct HxStreams {
    cudaStream_t s1 = 0, s2 = 0;
    cudaEvent_t evA = 0, ev1 = 0, ev2 = 0;
    bool ok = false;
    HxStreams() {
        ok = (cudaStreamCreateWithFlags(&s1, cudaStreamNonBlocking) == cudaSuccess) &&
             (cudaStreamCreateWithFlags(&s2, cudaStreamNonBlocking) == cudaSuccess) &&
             (cudaEventCreateWithFlags(&evA, cudaEventDisableTiming) == cudaSuccess) &&
             (cudaEventCreateWithFlags(&ev1, cudaEventDisableTiming) == cudaSuccess) &&
             (cudaEventCreateWithFlags(&ev2, cudaEventDisableTiming) == cudaSuccess);
    }
};
static HxStreams g_hx;

// ---------------------------------------------------------------------------
__device__ __forceinline__ u32 s2u(const void* p) {
    u32 a;
    asm("{ .reg .u64 t; cvta.to.shared.u64 t, %1; cvt.u32.u64 %0, t; }"
        : "=r"(a) : "l"(p));
    return a;
}
__device__ __forceinline__ void split2(float x, float y, u32& h, u32& l) {
    __nv_bfloat162 hb = __float22bfloat162_rn(make_float2(x, y));
    u32 hu = *reinterpret_cast<u32*>(&hb);
    float xh = __uint_as_float(hu << 16);
    float yh = __uint_as_float(hu & 0xffff0000u);
    __nv_bfloat162 lb = __float22bfloat162_rn(make_float2(x - xh, y - yh));
    h = hu;
    l = *reinterpret_cast<u32*>(&lb);
}

#define CPA16(dst_u32, src_ptr) \
    asm volatile("cp.async.cg.shared.global [%0], [%1], 16;" \
        :: "r"(dst_u32), "l"(src_ptr) : "memory")
#define CPA_COMMIT()   asm volatile("cp.async.commit_group;" ::: "memory")
#define CPA_WAITG1()   asm volatile("cp.async.wait_group 1;" ::: "memory")
#define CPA_WAIT_ALL() asm volatile("cp.async.wait_all;" ::: "memory")

#define LDSM4(r, addr) \
    asm volatile("ldmatrix.sync.aligned.m8n8.x4.shared.b16 {%0,%1,%2,%3}, [%4];" \
        : "=r"((r)[0]), "=r"((r)[1]), "=r"((r)[2]), "=r"((r)[3]) : "r"(addr))
#define LDSM2(r, addr) \
    asm volatile("ldmatrix.sync.aligned.m8n8.x2.shared.b16 {%0,%1}, [%2];" \
        : "=r"((r)[0]), "=r"((r)[1]) : "r"(addr))
#define MMA16816(d, a, b) \
    asm volatile("mma.sync.aligned.m16n8k16.row.col.f32.bf16.bf16.f32 " \
        "{%0,%1,%2,%3}, {%4,%5,%6,%7}, {%8,%9}, {%0,%1,%2,%3};" \
        : "+f"((d)[0]), "+f"((d)[1]), "+f"((d)[2]), "+f"((d)[3]) \
        : "r"((a)[0]), "r"((a)[1]), "r"((a)[2]), "r"((a)[3]), \
          "r"((b)[0]), "r"((b)[1]))

__device__ __forceinline__ void red4(float* p, float a, float b, float c, float d) {
    asm volatile("red.global.add.v4.f32 [%0], {%1, %2, %3, %4};"
                 :: "l"(p), "f"(a), "f"(b), "f"(c), "f"(d) : "memory");
}

// ---------------------------------------------------------------------------
// stage weight K-chunk kt (N rows x 16 u16, both planes) into 3-stage ring.
// chunk plane layout: [N][24] u16 (48B stride: 16B-aligned + ldmatrix
// conflict-free). ALL threads call (uniform commit).
// ---------------------------------------------------------------------------
#define CSTR 24
template<int N, int KPW>
__device__ __forceinline__ void stage_chunk(u32 cbase, int buf,
                                            const u16* __restrict__ Wh,
                                            const u16* __restrict__ Wl,
                                            int kt, int tid) {
    constexpr int CH = N * CSTR;   // u16 per plane per stage
    const u32 dstb = cbase + (u32)(buf * 2 * CH * 2);
    for (int idx = tid; idx < N * 4; idx += 512) {
        int row = idx >> 2, plane = (idx >> 1) & 1, half = idx & 1;
        const u16* src = (plane ? Wl : Wh) + row * KPW + kt * 16 + half * 8;
        CPA16(dstb + (u32)((plane * CH + row * CSTR + half * 8) * 2), src);
    }
    CPA_COMMIT();
}

// ---------------------------------------------------------------------------
// streamed-B 2D warp GEMM: C[ROWS,N] += X[ROWS,K] @ Wt[N,K]^T, 3-pass split.
// Prologue (chunks 0,1 staged + landed) must precede. One barrier per kt.
// ---------------------------------------------------------------------------
template<int K, int N, int NG, int KPX, int KPW>
__device__ __forceinline__ void warp_gemm_stream(u32 xh, u32 xl, u32 cbase,
                                                 const u16* __restrict__ Wh,
                                                 const u16* __restrict__ Wl,
                                                 int mg, int ng, int lane, int tid,
                                                 float* acc) {
    constexpr int KT  = K / 16;
    constexpr int NPW = N / NG;
    constexpr int NTW = NPW / 8;
    constexpr int CH  = N * CSTR;
    const u32 aoff = (u32)(((mg * 32 + (lane & 15)) * KPX + (lane >> 4) * 8) * 2);
    const u32 boff = (u32)((((ng * NPW) + (lane & 7)) * CSTR + ((lane >> 3) & 1) * 8) * 2);
    #pragma unroll
    for (int kt = 0; kt < KT; kt++) {
        CPA_WAITG1();
        __syncthreads();
        if (kt + 2 < KT) stage_chunk<N, KPW>(cbase, (kt + 2) % 3, Wh, Wl, kt + 2, tid);
        else CPA_COMMIT();   // keep group aging uniform
        const u32 cb = cbase + (u32)((kt % 3) * 2 * CH * 2);
        u32 A[2][2][4];
        #pragma unroll
        for (int mtl = 0; mtl < 2; mtl++) {
            u32 o = aoff + (u32)((mtl * 16 * KPX + kt * 16) * 2);
            LDSM4(A[0][mtl], xh + o);
            LDSM4(A[1][mtl], xl + o);
        }
        #pragma unroll
        for (int nt = 0; nt < NTW; nt++) {
            u32 o = boff + (u32)(nt * 8 * CSTR * 2);
            u32 Bh[2], Bl[2];
            LDSM2(Bh, cb + o);
            LDSM2(Bl, cb + (u32)(CH * 2) + o);
            #pragma unroll
            for (int mtl = 0; mtl < 2; mtl++) {
                float* d = acc + (mtl * NTW + nt) * 4;
                MMA16816(d, A[0][mtl], Bh);
                MMA16816(d, A[0][mtl], Bl);
                MMA16816(d, A[1][mtl], Bh);
            }
        }
    }
}

// ---------------------------------------------------------------------------
// merged weight prep + const precompute
// ---------------------------------------------------------------------------
__global__ void prep_const_all(const float* __restrict__ w0, const float* __restrict__ w1,
                               const float* __restrict__ w2, const float* __restrict__ w3,
                               const float* __restrict__ w4, const float* __restrict__ w5,
                               const float* __restrict__ w6, const float* __restrict__ w7,
                               const float* __restrict__ b11, const float* __restrict__ b12,
                               const float* __restrict__ b21, const float* __restrict__ b22,
                               const float* __restrict__ b31, const float* __restrict__ b32) {
    int b = blockIdx.x;
    if (b >= 574) {
        int pred = b - 574, j = threadIdx.x;
        const float *b1, *W2, *b2; int D, off;
        if (pred == 0)      { b1 = b11; W2 = w1; b2 = b12; D = 64;  off = 0;   }
        else if (pred == 1) { b1 = b21; W2 = w3; b2 = b22; D = 128; off = 64;  }
        else                { b1 = b31; W2 = w5; b2 = b32; D = 192; off = 192; }
        if (j < D) {
            float s = 0.f;
            for (int k = 0; k < D; k++) s = fmaf(fmaxf(b1[k], 0.f), W2[k * D + j], s);
            g_const[off + j] = s + b2[j];
        }
        return;
    }
    const float* W; int K, N, oh, ol, b0;
    if      (b < 18)  { W = w0; K = 64;  N = 64;  oh = 0;      ol = 4608;   b0 = 0;   }
    else if (b < 36)  { W = w1; K = 64;  N = 64;  oh = 9216;   ol = 13824;  b0 = 18;  }
    else if (b < 104) { W = w2; K = 128; N = 128; oh = 18432;  ol = 35840;  b0 = 36;  }
    else if (b < 172) { W = w3; K = 128; N = 128; oh = 53248;  ol = 70656;  b0 = 104; }
    else if (b < 322) { W = w4; K = 192; N = 192; oh = 88064;  ol = 126464; b0 = 172; }
    else if (b < 472) { W = w5; K = 192; N = 192; oh = 164864; ol = 203264; b0 = 322; }
    else if (b < 540) { W = w6; K = 128; N = 128; oh = 241664; ol = 259072; b0 = 472; }
    else              { W = w7; K = 128; N = 64;  oh = 276480; ol = 285184; b0 = 540; }
    int i = (b - b0) * 256 + threadIdx.x;
    int KP = K + 8;
    if (i >= N * KP) return;
    int n = i / KP, k = i - n * KP;
    u16 hv = 0, lv = 0;
    if (k < K) {
        float v = W[k * N + n];
        __nv_bfloat16 h = __float2bfloat16(v);
        __nv_bfloat16 l = __float2bfloat16(v - __bfloat162float(h));
        hv = *reinterpret_cast<u16*>(&h);
        lv = *reinterpret_cast<u16*>(&l);
    }
    g_wbuf[oh + i] = hv;
    g_wbuf[ol + i] = lv;
}

__global__ void deg_all_kernel(const int* __restrict__ ei1, int n1,
                               const int* __restrict__ ei2, int n2,
                               const int* __restrict__ ei3, int n3) {
    int s = blockIdx.y;
    int i = blockIdx.x * 256 + threadIdx.x;
    const int* e; int n, row;
    if (s == 0)     { e = ei1; n = n1; row = 0; }
    else if (s < 3) { e = ei2; n = n2; row = s - 1; }
    else            { e = ei3; n = n3; row = s - 3; }
    if (i < n) atomicAdd(&g_deg[s * MAX_OBJ + e[row * n + i]], 1);
}

// ---------------------------------------------------------------------------
// fused predicate kernel: ROWS atoms/block, 512 threads, streamed weights.
// ---------------------------------------------------------------------------
template<int R, int ROWS>
__global__ void __launch_bounds__(512, 2)
pred_mma_kernel(const int* __restrict__ ei, int nAtoms,
                const u16* __restrict__ W1h, const u16* __restrict__ W1l,
                const u16* __restrict__ W2h, const u16* __restrict__ W2l,
                const float* __restrict__ b1, const float* __restrict__ b2) {
    constexpr int D   = 64 * R;
    constexpr int KP  = D + 8;
    constexpr int NG  = 16 / (ROWS / 32);
    constexpr int NPW = D / NG;
    constexpr int NTW = NPW / 8;
    constexpr int TPA = 512 / ROWS;
    constexpr int U4  = 8 / TPA;
    constexpr int CHB = 3 * 2 * D * CSTR * 2;   // chunk ring bytes
    constexpr int XB  = ROWS * KP * 2;
    constexpr int FP  = D + 4;

    extern __shared__ char sm[];
    const u32 su = s2u(sm);
    const u32 cbase = su;
    const u32 XHa = su + CHB, XLa = XHa + XB;
    char* xh_c = sm + CHB;
    char* xl_c = xh_c + XB;
    float* b1s = (float*)(xh_c + 2 * XB);
    float* b2s = b1s + D;
    int*   es  = (int*)(b2s + D);
    float* F   = (float*)xh_c;

    const int tid = threadIdx.x, warp = tid >> 5, lane = tid & 31;
    const int ng = warp % NG, mg = warp / NG;
    const int base = blockIdx.x * ROWS;

    for (int i = tid; i < D; i += 512) { b1s[i] = b1[i]; b2s[i] = b2[i]; }
    if (tid < R * ROWS) {
        int s = tid / ROWS, a = tid % ROWS;
        int ga = base + a;
        es[tid] = (ga < nAtoms) ? ei[s * nAtoms + ga] : 0;
    }
    __syncthreads();   // es visible

    {   // gather via cp.async from pre-split planes
        int a = tid / TPA, h = tid % TPA;
        #pragma unroll
        for (int s = 0; s < R; s++) {
            size_t rb = (size_t)es[s * ROWS + a] * 8 + h * U4;
            u32 bo = (u32)(a * KP + s * 64 + h * (64 / TPA)) * 2;
            #pragma unroll
            for (int q = 0; q < U4; q++) {
                CPA16(XHa + bo + q * 16, (const uint4*)g_objh + rb + q);
                CPA16(XLa + bo + q * 16, (const uint4*)g_objl + rb + q);
            }
        }
    }
    stage_chunk<D, KP>(cbase, 0, W1h, W1l, 0, tid);
    stage_chunk<D, KP>(cbase, 1, W1h, W1l, 1, tid);
    CPA_WAIT_ALL();
    __syncthreads();

    float acc[2 * NTW * 4];
    #pragma unroll
    for (int i = 0; i < 2 * NTW * 4; i++) acc[i] = 0.f;
    warp_gemm_stream<D, D, NG, KP, KP>(XHa, XLa, cbase, W1h, W1l, mg, ng, lane, tid, acc);
    __syncthreads();   // all computes done; chunk ring free

    // prologue for GEMM2 overlaps epilogue1
    stage_chunk<D, KP>(cbase, 0, W2h, W2l, 0, tid);
    stage_chunk<D, KP>(cbase, 1, W2h, W2l, 1, tid);

    #pragma unroll
    for (int mtl = 0; mtl < 2; mtl++)
        #pragma unroll
        for (int nt = 0; nt < NTW; nt++) {
            float* d = acc + (mtl * NTW + nt) * 4;
            int row = mg * 32 + mtl * 16 + (lane >> 2);
            int col = ng * NPW + nt * 8 + 2 * (lane & 3);
            u32 hh, ll;
            float x0 = fmaxf(d[0] + b1s[col], 0.f), x1 = fmaxf(d[1] + b1s[col + 1], 0.f);
            split2(x0, x1, hh, ll);
            *(u32*)(xh_c + (row * KP + col) * 2) = hh;
            *(u32*)(xl_c + (row * KP + col) * 2) = ll;
            float x2 = fmaxf(d[2] + b1s[col], 0.f), x3 = fmaxf(d[3] + b1s[col + 1], 0.f);
            split2(x2, x3, hh, ll);
            *(u32*)(xh_c + ((row + 8) * KP + col) * 2) = hh;
            *(u32*)(xl_c + ((row + 8) * KP + col) * 2) = ll;
        }

    #pragma unroll
    for (int i = 0; i < 2 * NTW * 4; i++) acc[i] = 0.f;
    warp_gemm_stream<D, D, NG, KP, KP>(XHa, XLa, cbase, W2h, W2l, mg, ng, lane, tid, acc);
    __syncthreads();

    // epilogue2: C + b2 -> F
    #pragma unroll
    for (int mtl = 0; mtl < 2; mtl++)
        #pragma unroll
        for (int nt = 0; nt < NTW; nt++) {
            float* d = acc + (mtl * NTW + nt) * 4;
            int row = mg * 32 + mtl * 16 + (lane >> 2);
            int col = ng * NPW + nt * 8 + 2 * (lane & 3);
            *(float2*)(F + row * FP + col) =
                make_float2(d[0] + b2s[col], d[1] + b2s[col + 1]);
            *(float2*)(F + (row + 8) * FP + col) =
                make_float2(d[2] + b2s[col], d[3] + b2s[col + 1]);
        }
    __syncthreads();

    // scatter
    {
        int a = tid % ROWS, part = tid / ROWS;
        if (base + a < nAtoms) {
            #pragma unroll
            for (int j = part * (D / TPA); j < part * (D / TPA) + D / TPA; j += 4) {
                float* dst = g_agg + (size_t)es[(j >> 6) * ROWS + a] * HID + (j & 63);
                const float* f = F + a * FP + j;
                red4(dst, f[0], f[1], f[2], f[3]);
            }
        }
    }
}

// ---------------------------------------------------------------------------
// object update: 128 objects/block, 512 threads, 4Mx4N, streamed weights.
// Zeroes g_agg rows it owns (removes zero_agg kernels).
// ---------------------------------------------------------------------------
template<bool L1>
__global__ void __launch_bounds__(512, 2)
update_mma_kernel(const u16* __restrict__ U1h, const u16* __restrict__ U1l,
                  const u16* __restrict__ U2h, const u16* __restrict__ U2l,
                  const float* __restrict__ bu1, const float* __restrict__ bu2,
                  int nObj) {
    constexpr int KP  = 136;
    constexpr int CHB = 3 * 2 * 128 * CSTR * 2;   // ring sized for N=128
    constexpr int XB  = 128 * KP * 2;
    constexpr int FP  = 68;

    extern __shared__ char sm[];
    const u32 su = s2u(sm);
    const u32 cbase = su;
    const u32 XHa = su + CHB, XLa = XHa + XB;
    char* xh_c = sm + CHB;
    char* xl_c = xh_c + XB;
    float* b1s = (float*)(xh_c + 2 * XB);
    float* b2s = b1s + 128;
    float* cs  = b2s + 64;
    float* F   = (float*)xh_c;

    const int tid = threadIdx.x, warp = tid >> 5, lane = tid & 31;
    const int ng = warp & 3, mg = warp >> 2;
    const int base = blockIdx.x * 128;

    if (tid < 128) b1s[tid] = bu1[tid];
    else if (tid < 192) b2s[tid - 128] = bu2[tid - 128];
    if (L1) { for (int i = tid; i < 384; i += 512) cs[i] = g_const[i]; }
    if (L1) __syncthreads();

    {   // gather cat(obj, agg): 4 threads per object (h: 0-1 obj, 2-3 agg)
        int a = tid >> 2, h = tid & 3;
        int go = base + a;
        int gc = (go < nObj) ? go : 0;
        if (h < 2) {
            u32 bo = (u32)(a * KP + h * 32) * 2;
            if (L1) {
                uint4 z = make_uint4(0, 0, 0, 0);
                #pragma unroll
                for (int q = 0; q < 4; q++) {
                    *(uint4*)(xh_c + bo + q * 16) = z;
                    *(uint4*)(xl_c + bo + q * 16) = z;
                }
            } else {
                size_t rb = (size_t)gc * 8 + h * 4;
                #pragma unroll
                for (int q = 0; q < 4; q++) {
                    CPA16(XHa + bo + q * 16, (const uint4*)g_objh + rb + q);
                    CPA16(XLa + bo + q * 16, (const uint4*)g_objl + rb + q);
                }
            }
        } else {
            int hh = h - 2;
            u32 bo = (u32)(a * KP + 64 + hh * 32) * 2;
            if (L1) {
                float degf[6];
                #pragma unroll
                for (int s = 0; s < 6; s++)
                    degf[s] = (float)g_deg[s * MAX_OBJ + gc];
                #pragma unroll
                for (int q = 0; q < 8; q++) {
                    float v[4];
                    #pragma unroll
                    for (int t = 0; t < 4; t++) {
                        int cc = hh * 32 + q * 4 + t;
                        float s = 0.f;
                        #pragma unroll
                        for (int p = 0; p < 6; p++) s = fmaf(degf[p], cs[p * 64 + cc], s);
                        v[t] = s;
                    }
                    u32 h0, l0, h1, l1;
                    split2(v[0], v[1], h0, l0);
                    split2(v[2], v[3], h1, l1);
                    *(u64*)(xh_c + bo + q * 8) = (u64)h0 | ((u64)h1 << 32);
                    *(u64*)(xl_c + bo + q * 8) = (u64)l0 | ((u64)l1 << 32);
                }
            } else {
                const float* src = g_agg + (size_t)gc * HID + hh * 32;
                #pragma unroll
                for (int q = 0; q < 8; q++) {
                    float4 v = *(const float4*)(src + q * 4);
                    u32 h0, l0, h1, l1;
                    split2(v.x, v.y, h0, l0);
                    split2(v.z, v.w, h1, l1);
                    *(u64*)(xh_c + bo + q * 8) = (u64)h0 | ((u64)h1 << 32);
                    *(u64*)(xl_c + bo + q * 8) = (u64)l0 | ((u64)l1 << 32);
                }
            }
            // zero g_agg for next layer (owner row only, after read)
            if (go < nObj) {
                float4 z4 = make_float4(0.f, 0.f, 0.f, 0.f);
                float* dst = g_agg + (size_t)go * HID + hh * 32;
                #pragma unroll
                for (int q = 0; q < 8; q++) *(float4*)(dst + q * 4) = z4;
            }
        }
    }
    stage_chunk<128, KP>(cbase, 0, U1h, U1l, 0, tid);
    stage_chunk<128, KP>(cbase, 1, U1h, U1l, 1, tid);
    CPA_WAIT_ALL();
    __syncthreads();

    float acc[2 * 4 * 4];
    #pragma unroll
    for (int i = 0; i < 32; i++) acc[i] = 0.f;
    warp_gemm_stream<128, 128, 4, KP, KP>(XHa, XLa, cbase, U1h, U1l, mg, ng, lane, tid, acc);
    __syncthreads();

    stage_chunk<64, KP>(cbase, 0, U2h, U2l, 0, tid);
    stage_chunk<64, KP>(cbase, 1, U2h, U2l, 1, tid);

    // epilogue1 -> H
    #pragma unroll
    for (int mtl = 0; mtl < 2; mtl++)
        #pragma unroll
        for (int nt = 0; nt < 4; nt++) {
            float* d = acc + (mtl * 4 + nt) * 4;
            int row = mg * 32 + mtl * 16 + (lane >> 2);
            int col = ng * 32 + nt * 8 + 2 * (lane & 3);
            u32 hh, ll;
            float x0 = fmaxf(d[0] + b1s[col], 0.f), x1 = fmaxf(d[1] + b1s[col + 1], 0.f);
            split2(x0, x1, hh, ll);
            *(u32*)(xh_c + (row * KP + col) * 2) = hh;
            *(u32*)(xl_c + (row * KP + col) * 2) = ll;
            float x2 = fmaxf(d[2] + b1s[col], 0.f), x3 = fmaxf(d[3] + b1s[col + 1], 0.f);
            split2(x2, x3, hh, ll);
            *(u32*)(xh_c + ((row + 8) * KP + col) * 2) = hh;
            *(u32*)(xl_c + ((row + 8) * KP + col) * 2) = ll;
        }

    #pragma unroll
    for (int i = 0; i < 16; i++) acc[i] = 0.f;
    warp_gemm_stream<128, 64, 4, KP, KP>(XHa, XLa, cbase, U2h, U2l, mg, ng, lane, tid, acc);
    __syncthreads();

    // epilogue2 -> F (f32 [128][68])
    #pragma unroll
    for (int mtl = 0; mtl < 2; mtl++)
        #pragma unroll
        for (int nt = 0; nt < 2; nt++) {
            float* d = acc + (mtl * 2 + nt) * 4;
            int row = mg * 32 + mtl * 16 + (lane >> 2);
            int col = ng * 16 + nt * 8 + 2 * (lane & 3);
            *(float2*)(F + row * FP + col) =
                make_float2(d[0] + b2s[col], d[1] + b2s[col + 1]);
            *(float2*)(F + (row + 8) * FP + col) =
                make_float2(d[2] + b2s[col], d[3] + b2s[col + 1]);
        }
    __syncthreads();

    {   // write back: 4 threads/object, 16 cols each
        int a = tid >> 2, h = tid & 3;
        int go = base + a;
        if (go < nObj) {
            const float* f = F + a * FP + h * 16;
            float* dst = g_obj + (size_t)go * HID + h * 16;
            uint4 ph[2], pl[2];
            u32* phu = (u32*)ph; u32* plu = (u32*)pl;
            #pragma unroll
            for (int q = 0; q < 4; q++) {
                float4 v = *(const float4*)(f + q * 4);
                *(float4*)(dst + q * 4) = v;
                split2(v.x, v.y, phu[q * 2], plu[q * 2]);
                split2(v.z, v.w, phu[q * 2 + 1], plu[q * 2 + 1]);
            }
            uint4* dh = (uint4*)g_objh + (size_t)go * 8 + h * 2;
            uint4* dl = (uint4*)g_objl + (size_t)go * 8 + h * 2;
            dh[0] = ph[0]; dh[1] = ph[1];
            dl[0] = pl[0]; dl[1] = pl[1];
        }
    }
}

// ---------------------------------------------------------------------------
// small kernels
// ---------------------------------------------------------------------------
__global__ void zero_init_kernel(int nObj) {
    int i = blockIdx.x * 256 + threadIdx.x;
    if (i < 6 * MAX_OBJ)      g_deg[i] = 0;
    if (i < MAX_GRAPHS * HID) g_pooled[i] = 0.f;
    if (i < nObj * HID)       g_agg[i] = 0.f;   // first-run safety
}
__global__ void pool_kernel(const int* __restrict__ batch, int nObj) {
    int c = threadIdx.x;
    int base = blockIdx.x * 64;
    int end = min(base + 64, nObj);
    int cur = -1; float s = 0.f;
    for (int o = base; o < end; o++) {
        int b = batch[o];
        if (b != cur) {
            if (cur >= 0) atomicAdd(&g_pooled[cur * HID + c], s);
            cur = b; s = 0.f;
        }
        s += g_obj[(size_t)o * HID + c];
    }
    if (cur >= 0) atomicAdd(&g_pooled[cur * HID + c], s);
}
__global__ void readout_kernel(const float* __restrict__ w1, const float* __restrict__ b1,
                               const float* __restrict__ w2, const float* __restrict__ b2,
                               float* __restrict__ out) {
    __shared__ float p[64];
    __shared__ float red[4];
    int g = blockIdx.x, t = threadIdx.x;
    if (t < 64) p[t] = g_pooled[g * HID + t];
    __syncthreads();
    float acc = 0.f;
    #pragma unroll
    for (int k = 0; k < 64; k++) acc = fmaf(p[k], w1[k * 128 + t], acc);
    acc = fmaxf(acc + b1[t], 0.f) * w2[t];
    #pragma unroll
    for (int off = 16; off; off >>= 1) acc += __shfl_down_sync(0xffffffffu, acc, off);
    if ((t & 31) == 0) red[t >> 5] = acc;
    __syncthreads();
    if (t == 0) out[g] = red[0] + red[1] + red[2] + red[3] + b2[0];
}

// ---------------------------------------------------------------------------
extern "C" void kernel_launch(void* const* d_in, const int* in_sizes, int n_in,
                              void* d_out, int out_size) {
    const float* w_p1_1 = (const float*)d_in[4];
    const float* b_p1_1 = (const float*)d_in[5];
    const float* w_p1_2 = (const float*)d_in[6];
    const float* b_p1_2 = (const float*)d_in[7];
    const float* w_p2_1 = (const float*)d_in[8];
    const float* b_p2_1 = (const float*)d_in[9];
    const float* w_p2_2 = (const float*)d_in[10];
    const float* b_p2_2 = (const float*)d_in[11];
    const float* w_p3_1 = (const float*)d_in[12];
    const float* b_p3_1 = (const float*)d_in[13];
    const float* w_p3_2 = (const float*)d_in[14];
    const float* b_p3_2 = (const float*)d_in[15];
    const float* w_u1   = (const float*)d_in[16];
    const float* b_u1   = (const float*)d_in[17];
    const float* w_u2   = (const float*)d_in[18];
    const float* b_u2   = (const float*)d_in[19];
    const float* w_r1   = (const float*)d_in[20];
    const float* b_r1   = (const float*)d_in[21];
    const float* w_r2   = (const float*)d_in[22];
    const float* b_r2   = (const float*)d_in[23];
    const int*   ei_p1  = (const int*)d_in[24];
    const int*   ei_p2  = (const int*)d_in[25];
    const int*   ei_p3  = (const int*)d_in[26];
    const int*   batch  = (const int*)d_in[27];

    const int nObj = in_sizes[0];
    const int nP1  = in_sizes[24];
    const int nP2  = in_sizes[25] / 2;
    const int nP3  = in_sizes[26] / 3;
    const int nGraphs = out_size;
    float* out = (float*)d_out;

    u16* wb = nullptr;
    cudaGetSymbolAddress((void**)&wb, g_wbuf);

    // smem: CHB + 2*XB + biases + es
    const int smem1 = 3 * 2 * 64 * 24 * 2  + 2 * (128 * 72 * 2)  + 8 * 64  + 128 * 4;
    const int smem2 = 3 * 2 * 128 * 24 * 2 + 2 * (128 * 136 * 2) + 8 * 128 + 2 * 128 * 4;
    const int smem3 = 3 * 2 * 192 * 24 * 2 + 2 * (64 * 200 * 2)  + 8 * 192 + 3 * 64 * 4;
    const int smemU = 3 * 2 * 128 * 24 * 2 + 2 * (128 * 136 * 2) + 128 * 4 + 64 * 4 + 384 * 4;
    cudaFuncSetAttribute((pred_mma_kernel<1, 128>), cudaFuncAttributeMaxDynamicSharedMemorySize, smem1);
    cudaFuncSetAttribute((pred_mma_kernel<2, 128>), cudaFuncAttributeMaxDynamicSharedMemorySize, smem2);
    cudaFuncSetAttribute((pred_mma_kernel<3, 64>), cudaFuncAttributeMaxDynamicSharedMemorySize, smem3);
    cudaFuncSetAttribute(update_mma_kernel<true>, cudaFuncAttributeMaxDynamicSharedMemorySize, smemU);
    cudaFuncSetAttribute(update_mma_kernel<false>, cudaFuncAttributeMaxDynamicSharedMemorySize, smemU);

    const int bObj = (nObj + 127) / 128;
    const int bP1  = (nP1 + 127) / 128;
    const int bP2  = (nP2 + 127) / 128;
    const int bP3  = (nP3 + 63) / 64;
    int nmax = nP1 > nP2 ? nP1 : nP2; if (nP3 > nmax) nmax = nP3;

    int zn = nObj * HID; if (6 * MAX_OBJ > zn) zn = 6 * MAX_OBJ;
    zero_init_kernel<<<(zn + 255) / 256, 256>>>(nObj);                        // 0
    prep_const_all<<<577, 256>>>(w_p1_1, w_p1_2, w_p2_1, w_p2_2,              // 1
                                 w_p3_1, w_p3_2, w_u1, w_u2,
                                 b_p1_1, b_p1_2, b_p2_1, b_p2_2, b_p3_1, b_p3_2);
    deg_all_kernel<<<dim3((nmax + 255) / 256, 6), 256>>>(ei_p1, nP1,          // 2
                                                         ei_p2, nP2,
                                                         ei_p3, nP3);
    update_mma_kernel<true><<<bObj, 512, smemU>>>(wb + 241664, wb + 259072,   // 3
                                                  wb + 276480, wb + 285184,
                                                  b_u1, b_u2, nObj);

    const bool fork = g_hx.ok;
    cudaStream_t sA = fork ? g_hx.s1 : (cudaStream_t)0;
    cudaStream_t sB = fork ? g_hx.s2 : (cudaStream_t)0;

    for (int layer = 1; layer < 3; layer++) {
        if (fork) {
            cudaEventRecord(g_hx.evA, 0);
            cudaStreamWaitEvent(sA, g_hx.evA, 0);
            cudaStreamWaitEvent(sB, g_hx.evA, 0);
        }
        pred_mma_kernel<1, 128><<<bP1, 512, smem1, sA>>>(
            ei_p1, nP1, wb + 0, wb + 4608, wb + 9216, wb + 13824, b_p1_1, b_p1_2);
        pred_mma_kernel<2, 128><<<bP2, 512, smem2, sB>>>(
            ei_p2, nP2, wb + 18432, wb + 35840, wb + 53248, wb + 70656, b_p2_1, b_p2_2);
        pred_mma_kernel<3, 64><<<bP3, 512, smem3>>>(
            ei_p3, nP3, wb + 88064, wb + 126464, wb + 164864, wb + 203264, b_p3_1, b_p3_2);
        if (fork) {
            cudaEventRecord(g_hx.ev1, sA);
            cudaEventRecord(g_hx.ev2, sB);
            cudaStreamWaitEvent((cudaStream_t)0, g_hx.ev1, 0);
            cudaStreamWaitEvent((cudaStream_t)0, g_hx.ev2, 0);
        }
        update_mma_kernel<false><<<bObj, 512, smemU>>>(wb + 241664, wb + 259072,
                                                       wb + 276480, wb + 285184,
                                                       b_u1, b_u2, nObj);
    }

    pool_kernel<<<(nObj + 63) / 64, 64>>>(batch, nObj);
    readout_kernel<<<nGraphs, 128>>>(w_r1, b_r1, w_r2, b_r2, out);
}

// round 15
// speedup vs baseline: 1.2363x; 1.2363x over previous
#include <cuda_runtime.h>
#include <cuda_bf16.h>

#define HID 64
#define MAX_OBJ 100000
#define MAX_GRAPHS 256

typedef unsigned int u32;
typedef unsigned long long u64;
typedef unsigned short u16;

__device__ float g_obj[MAX_OBJ * HID];
__device__ float g_agg[MAX_OBJ * HID];
__device__ int   g_deg[6 * MAX_OBJ];
__device__ float g_const[64 + 128 + 192];
__device__ float g_pooled[MAX_GRAPHS * HID];

// pre-split bf16 planes of g_obj: row = 32 u32 = 8 uint4 (64 values)
__device__ __align__(16) u32 g_objh[MAX_OBJ * 32];
__device__ __align__(16) u32 g_objl[MAX_OBJ * 32];

// pre-transposed, bf16-split weights, layout [N][K+8] u16 per half.
__device__ __align__(16) u16 g_wbuf[293888];

// ---------------------------------------------------------------------------
struct HxStreams {
    cudaStream_t s1 = 0, s2 = 0;
    cudaEvent_t evA = 0, ev1 = 0, ev2 = 0;
    bool ok = false;
    HxStreams() {
        ok = (cudaStreamCreateWithFlags(&s1, cudaStreamNonBlocking) == cudaSuccess) &&
             (cudaStreamCreateWithFlags(&s2, cudaStreamNonBlocking) == cudaSuccess) &&
             (cudaEventCreateWithFlags(&evA, cudaEventDisableTiming) == cudaSuccess) &&
             (cudaEventCreateWithFlags(&ev1, cudaEventDisableTiming) == cudaSuccess) &&
             (cudaEventCreateWithFlags(&ev2, cudaEventDisableTiming) == cudaSuccess);
    }
};
static HxStreams g_hx;

// ---------------------------------------------------------------------------
__device__ __forceinline__ u32 s2u(const void* p) {
    u32 a;
    asm("{ .reg .u64 t; cvta.to.shared.u64 t, %1; cvt.u32.u64 %0, t; }"
        : "=r"(a) : "l"(p));
    return a;
}
__device__ __forceinline__ void split2(float x, float y, u32& h, u32& l) {
    __nv_bfloat162 hb = __float22bfloat162_rn(make_float2(x, y));
    u32 hu = *reinterpret_cast<u32*>(&hb);
    float xh = __uint_as_float(hu << 16);
    float yh = __uint_as_float(hu & 0xffff0000u);
    __nv_bfloat162 lb = __float22bfloat162_rn(make_float2(x - xh, y - yh));
    h = hu;
    l = *reinterpret_cast<u32*>(&lb);
}
__device__ __forceinline__ u32 pack_bf2(float x, float y) {
    __nv_bfloat162 hb = __float22bfloat162_rn(make_float2(x, y));
    return *reinterpret_cast<u32*>(&hb);
}

#define CPA16(dst_u32, src_ptr) \
    asm volatile("cp.async.cg.shared.global [%0], [%1], 16;" \
        :: "r"(dst_u32), "l"(src_ptr) : "memory")
#define CPA_WAIT_ALL() asm volatile("cp.async.wait_all;" ::: "memory")

#define LDSM4(r, addr) \
    asm volatile("ldmatrix.sync.aligned.m8n8.x4.shared.b16 {%0,%1,%2,%3}, [%4];" \
        : "=r"((r)[0]), "=r"((r)[1]), "=r"((r)[2]), "=r"((r)[3]) : "r"(addr))
#define LDSM2(r, addr) \
    asm volatile("ldmatrix.sync.aligned.m8n8.x2.shared.b16 {%0,%1}, [%2];" \
        : "=r"((r)[0]), "=r"((r)[1]) : "r"(addr))
#define MMA16816(d, a, b) \
    asm volatile("mma.sync.aligned.m16n8k16.row.col.f32.bf16.bf16.f32 " \
        "{%0,%1,%2,%3}, {%4,%5,%6,%7}, {%8,%9}, {%0,%1,%2,%3};" \
        : "+f"((d)[0]), "+f"((d)[1]), "+f"((d)[2]), "+f"((d)[3]) \
        : "r"((a)[0]), "r"((a)[1]), "r"((a)[2]), "r"((a)[3]), \
          "r"((b)[0]), "r"((b)[1]))

__device__ __forceinline__ void red4(float* p, float a, float b, float c, float d) {
    asm volatile("red.global.add.v4.f32 [%0], {%1, %2, %3, %4};"
                 :: "l"(p), "f"(a), "f"(b), "f"(c), "f"(d) : "memory");
}

// ---------------------------------------------------------------------------
// 3-pass split GEMM (A hi+lo, B hi+lo): used by update (full precision).
// ---------------------------------------------------------------------------
template<int K, int N, int NG>
__device__ __forceinline__ void warp_gemm3(u32 xh, u32 xl, u32 wh, u32 wl,
                                           int mg, int ng, int lane, float* acc) {
    constexpr int KP  = K + 8;
    constexpr int NPW = N / NG;
    constexpr int NTW = NPW / 8;
    const u32 aoff = (u32)(((mg * 32 + (lane & 15)) * KP + (lane >> 4) * 8) * 2);
    const u32 boff = (u32)((((ng * NPW) + (lane & 7)) * KP + ((lane >> 3) & 1) * 8) * 2);
    #pragma unroll
    for (int kt = 0; kt < K / 16; kt++) {
        u32 A[2][2][4];
        #pragma unroll
        for (int mtl = 0; mtl < 2; mtl++) {
            u32 o = aoff + (u32)((mtl * 16 * KP + kt * 16) * 2);
            LDSM4(A[0][mtl], xh + o);
            LDSM4(A[1][mtl], xl + o);
        }
        #pragma unroll
        for (int nt = 0; nt < NTW; nt++) {
            u32 o = boff + (u32)((nt * 8 * KP + kt * 16) * 2);
            u32 Bh[2], Bl[2];
            LDSM2(Bh, wh + o);
            LDSM2(Bl, wl + o);
            #pragma unroll
            for (int mtl = 0; mtl < 2; mtl++) {
                float* d = acc + (mtl * NTW + nt) * 4;
                MMA16816(d, A[0][mtl], Bh);
                MMA16816(d, A[0][mtl], Bl);
                MMA16816(d, A[1][mtl], Bh);
            }
        }
    }
}

// ---------------------------------------------------------------------------
// 2-pass split GEMM (A bf16 single-plane, B hi+lo): used by predicates.
// error ~2^-9 * kappa (measured kappa ~0.13 => ~3e-4, within 1e-3 gate)
// ---------------------------------------------------------------------------
template<int K, int N, int NG>
__device__ __forceinline__ void warp_gemm2(u32 xh, u32 wh, u32 wl,
                                           int mg, int ng, int lane, float* acc) {
    constexpr int KP  = K + 8;
    constexpr int NPW = N / NG;
    constexpr int NTW = NPW / 8;
    const u32 aoff = (u32)(((mg * 32 + (lane & 15)) * KP + (lane >> 4) * 8) * 2);
    const u32 boff = (u32)((((ng * NPW) + (lane & 7)) * KP + ((lane >> 3) & 1) * 8) * 2);
    #pragma unroll
    for (int kt = 0; kt < K / 16; kt++) {
        u32 A[2][4];
        #pragma unroll
        for (int mtl = 0; mtl < 2; mtl++) {
            u32 o = aoff + (u32)((mtl * 16 * KP + kt * 16) * 2);
            LDSM4(A[mtl], xh + o);
        }
        #pragma unroll
        for (int nt = 0; nt < NTW; nt++) {
            u32 o = boff + (u32)((nt * 8 * KP + kt * 16) * 2);
            u32 Bh[2], Bl[2];
            LDSM2(Bh, wh + o);
            LDSM2(Bl, wl + o);
            #pragma unroll
            for (int mtl = 0; mtl < 2; mtl++) {
                float* d = acc + (mtl * NTW + nt) * 4;
                MMA16816(d, A[mtl], Bh);
                MMA16816(d, A[mtl], Bl);
            }
        }
    }
}

// ---------------------------------------------------------------------------
// merged weight prep + const precompute
// ---------------------------------------------------------------------------
__global__ void prep_const_all(const float* __restrict__ w0, const float* __restrict__ w1,
                               const float* __restrict__ w2, const float* __restrict__ w3,
                               const float* __restrict__ w4, const float* __restrict__ w5,
                               const float* __restrict__ w6, const float* __restrict__ w7,
                               const float* __restrict__ b11, const float* __restrict__ b12,
                               const float* __restrict__ b21, const float* __restrict__ b22,
                               const float* __restrict__ b31, const float* __restrict__ b32) {
    int b = blockIdx.x;
    if (b >= 574) {
        int pred = b - 574, j = threadIdx.x;
        const float *b1, *W2, *b2; int D, off;
        if (pred == 0)      { b1 = b11; W2 = w1; b2 = b12; D = 64;  off = 0;   }
        else if (pred == 1) { b1 = b21; W2 = w3; b2 = b22; D = 128; off = 64;  }
        else                { b1 = b31; W2 = w5; b2 = b32; D = 192; off = 192; }
        if (j < D) {
            float s = 0.f;
            for (int k = 0; k < D; k++) s = fmaf(fmaxf(b1[k], 0.f), W2[k * D + j], s);
            g_const[off + j] = s + b2[j];
        }
        return;
    }
    const float* W; int K, N, oh, ol, b0;
    if      (b < 18)  { W = w0; K = 64;  N = 64;  oh = 0;      ol = 4608;   b0 = 0;   }
    else if (b < 36)  { W = w1; K = 64;  N = 64;  oh = 9216;   ol = 13824;  b0 = 18;  }
    else if (b < 104) { W = w2; K = 128; N = 128; oh = 18432;  ol = 35840;  b0 = 36;  }
    else if (b < 172) { W = w3; K = 128; N = 128; oh = 53248;  ol = 70656;  b0 = 104; }
    else if (b < 322) { W = w4; K = 192; N = 192; oh = 88064;  ol = 126464; b0 = 172; }
    else if (b < 472) { W = w5; K = 192; N = 192; oh = 164864; ol = 203264; b0 = 322; }
    else if (b < 540) { W = w6; K = 128; N = 128; oh = 241664; ol = 259072; b0 = 472; }
    else              { W = w7; K = 128; N = 64;  oh = 276480; ol = 285184; b0 = 540; }
    int i = (b - b0) * 256 + threadIdx.x;
    int KP = K + 8;
    if (i >= N * KP) return;
    int n = i / KP, k = i - n * KP;
    u16 hv = 0, lv = 0;
    if (k < K) {
        float v = W[k * N + n];
        __nv_bfloat16 h = __float2bfloat16(v);
        __nv_bfloat16 l = __float2bfloat16(v - __bfloat162float(h));
        hv = *reinterpret_cast<u16*>(&h);
        lv = *reinterpret_cast<u16*>(&l);
    }
    g_wbuf[oh + i] = hv;
    g_wbuf[ol + i] = lv;
}

__global__ void deg_all_kernel(const int* __restrict__ ei1, int n1,
                               const int* __restrict__ ei2, int n2,
                               const int* __restrict__ ei3, int n3) {
    int s = blockIdx.y;
    int i = blockIdx.x * 256 + threadIdx.x;
    const int* e; int n, row;
    if (s == 0)     { e = ei1; n = n1; row = 0; }
    else if (s < 3) { e = ei2; n = n2; row = s - 1; }
    else            { e = ei3; n = n3; row = s - 3; }
    if (i < n) atomicAdd(&g_deg[s * MAX_OBJ + e[row * n + i]], 1);
}

// ---------------------------------------------------------------------------
// fused predicate kernel: single-plane A, 2-pass GEMMs.
// BOTH: stage W1+W2 up-front; else stage W2 overlapped with epilogue1.
// ---------------------------------------------------------------------------
template<int R, int ROWS, int MAXB, bool BOTH>
__global__ void __launch_bounds__(512, MAXB)
pred_mma_kernel(const int* __restrict__ ei, int nAtoms,
                const u16* __restrict__ W1h, const u16* __restrict__ W1l,
                const u16* __restrict__ W2h, const u16* __restrict__ W2l,
                const float* __restrict__ b1, const float* __restrict__ b2) {
    constexpr int D   = 64 * R;
    constexpr int KP  = D + 8;
    constexpr int NG  = 16 / (ROWS / 32);
    constexpr int NPW = D / NG;
    constexpr int NTW = NPW / 8;
    constexpr int TPA = 512 / ROWS;
    constexpr int U4  = 8 / TPA;
    constexpr int WB  = D * KP * 2;
    constexpr int XB  = ROWS * KP * 2;     // one plane; region is 2*XB (X + F)
    constexpr int FP  = D + 4;
    constexpr int NWB = BOTH ? 4 : 2;

    extern __shared__ char sm[];
    const u32 su = s2u(sm);
    const u32 W1H = su, W1L = su + WB;
    const u32 W2H = BOTH ? su + 2 * WB : su;
    const u32 W2L = BOTH ? su + 3 * WB : su + WB;
    const u32 XHa = su + NWB * WB;
    char* xh_c = sm + NWB * WB;
    float* b1s = (float*)(sm + NWB * WB + 2 * XB);
    float* b2s = b1s + D;
    int*   es  = (int*)(b2s + D);
    float* F   = (float*)(sm + NWB * WB);   // overlays X region (2*XB >= F)

    const int tid = threadIdx.x, warp = tid >> 5, lane = tid & 31;
    const int ng = warp % NG, mg = warp / NG;
    const int base = blockIdx.x * ROWS;

    for (int i = tid * 16; i < WB; i += 512 * 16) {
        CPA16(W1H + i, (const char*)W1h + i);
        CPA16(W1L + i, (const char*)W1l + i);
        if (BOTH) {
            CPA16(W2H + i, (const char*)W2h + i);
            CPA16(W2L + i, (const char*)W2l + i);
        }
    }
    for (int i = tid; i < D; i += 512) { b1s[i] = b1[i]; b2s[i] = b2[i]; }
    if (tid < R * ROWS) {
        int s = tid / ROWS, a = tid % ROWS;
        int ga = base + a;
        es[tid] = (ga < nAtoms) ? ei[s * nAtoms + ga] : 0;
    }
    __syncthreads();   // es visible

    {   // gather hi plane only
        int a = tid / TPA, h = tid % TPA;
        #pragma unroll
        for (int s = 0; s < R; s++) {
            size_t rb = (size_t)es[s * ROWS + a] * 8 + h * U4;
            u32 bo = (u32)(a * KP + s * 64 + h * (64 / TPA)) * 2;
            #pragma unroll
            for (int q = 0; q < U4; q++)
                CPA16(XHa + bo + q * 16, (const uint4*)g_objh + rb + q);
        }
    }
    CPA_WAIT_ALL();
    __syncthreads();

    float acc[2 * NTW * 4];
    #pragma unroll
    for (int i = 0; i < 2 * NTW * 4; i++) acc[i] = 0.f;
    warp_gemm2<D, D, NG>(XHa, W1H, W1L, mg, ng, lane, acc);
    __syncthreads();

    if (!BOTH) {
        for (int i = tid * 16; i < WB; i += 512 * 16) {
            CPA16(W2H + i, (const char*)W2h + i);
            CPA16(W2L + i, (const char*)W2l + i);
        }
    }
    // epilogue1: H = relu(C + b1) -> hi plane only
    #pragma unroll
    for (int mtl = 0; mtl < 2; mtl++)
        #pragma unroll
        for (int nt = 0; nt < NTW; nt++) {
            float* d = acc + (mtl * NTW + nt) * 4;
            int row = mg * 32 + mtl * 16 + (lane >> 2);
            int col = ng * NPW + nt * 8 + 2 * (lane & 3);
            float x0 = fmaxf(d[0] + b1s[col], 0.f), x1 = fmaxf(d[1] + b1s[col + 1], 0.f);
            *(u32*)(xh_c + (row * KP + col) * 2) = pack_bf2(x0, x1);
            float x2 = fmaxf(d[2] + b1s[col], 0.f), x3 = fmaxf(d[3] + b1s[col + 1], 0.f);
            *(u32*)(xh_c + ((row + 8) * KP + col) * 2) = pack_bf2(x2, x3);
        }
    if (!BOTH) CPA_WAIT_ALL();
    __syncthreads();

    #pragma unroll
    for (int i = 0; i < 2 * NTW * 4; i++) acc[i] = 0.f;
    warp_gemm2<D, D, NG>(XHa, W2H, W2L, mg, ng, lane, acc);
    __syncthreads();

    // epilogue2: C + b2 -> F
    #pragma unroll
    for (int mtl = 0; mtl < 2; mtl++)
        #pragma unroll
        for (int nt = 0; nt < NTW; nt++) {
            float* d = acc + (mtl * NTW + nt) * 4;
            int row = mg * 32 + mtl * 16 + (lane >> 2);
            int col = ng * NPW + nt * 8 + 2 * (lane & 3);
            *(float2*)(F + row * FP + col) =
                make_float2(d[0] + b2s[col], d[1] + b2s[col + 1]);
            *(float2*)(F + (row + 8) * FP + col) =
                make_float2(d[2] + b2s[col], d[3] + b2s[col + 1]);
        }
    __syncthreads();

    // scatter
    {
        int a = tid % ROWS, part = tid / ROWS;
        if (base + a < nAtoms) {
            #pragma unroll
            for (int j = part * (D / TPA); j < part * (D / TPA) + D / TPA; j += 4) {
                float* dst = g_agg + (size_t)es[(j >> 6) * ROWS + a] * HID + (j & 63);
                const float* f = F + a * FP + j;
                red4(dst, f[0], f[1], f[2], f[3]);
            }
        }
    }
}

// ---------------------------------------------------------------------------
// object update: 128 objects/block, 512 threads, 4Mx4N, 3-pass (full precision)
// U1+U2 staged up-front. (R12 structure.)
// ---------------------------------------------------------------------------
template<bool L1>
__global__ void __launch_bounds__(512, 1)
update_mma_kernel(const u16* __restrict__ U1h, const u16* __restrict__ U1l,
                  const u16* __restrict__ U2h, const u16* __restrict__ U2l,
                  const float* __restrict__ bu1, const float* __restrict__ bu2,
                  int nObj) {
    constexpr int KP  = 136;
    constexpr int WB1 = 128 * KP * 2;
    constexpr int WB2 = 64 * KP * 2;
    constexpr int XB  = 128 * KP * 2;
    constexpr int FP  = 68;

    extern __shared__ char sm[];
    const u32 su = s2u(sm);
    const u32 U1H = su, U1L = su + WB1;
    const u32 U2H = su + 2 * WB1, U2L = su + 2 * WB1 + WB2;
    const u32 XHa = su + 2 * WB1 + 2 * WB2, XLa = XHa + XB;
    char* xh_c = sm + 2 * WB1 + 2 * WB2;
    char* xl_c = xh_c + XB;
    float* b1s = (float*)(xh_c + 2 * XB);
    float* b2s = b1s + 128;
    float* cs  = b2s + 64;
    float* F   = (float*)xh_c;

    const int tid = threadIdx.x, warp = tid >> 5, lane = tid & 31;
    const int ng = warp & 3, mg = warp >> 2;
    const int base = blockIdx.x * 128;

    for (int i = tid * 16; i < WB1; i += 512 * 16) {
        CPA16(U1H + i, (const char*)U1h + i);
        CPA16(U1L + i, (const char*)U1l + i);
    }
    for (int i = tid * 16; i < WB2; i += 512 * 16) {
        CPA16(U2H + i, (const char*)U2h + i);
        CPA16(U2L + i, (const char*)U2l + i);
    }
    if (tid < 128) b1s[tid] = bu1[tid];
    else if (tid < 192) b2s[tid - 128] = bu2[tid - 128];
    if (L1) { for (int i = tid; i < 384; i += 512) cs[i] = g_const[i]; }
    if (L1) __syncthreads();

    {   // gather cat(obj, agg): 4 threads per object
        int a = tid >> 2, h = tid & 3;
        int go = base + a;
        int gc = (go < nObj) ? go : 0;
        if (h < 2) {
            u32 bo = (u32)(a * KP + h * 32) * 2;
            if (L1) {
                uint4 z = make_uint4(0, 0, 0, 0);
                #pragma unroll
                for (int q = 0; q < 4; q++) {
                    *(uint4*)(xh_c + bo + q * 16) = z;
                    *(uint4*)(xl_c + bo + q * 16) = z;
                }
            } else {
                size_t rb = (size_t)gc * 8 + h * 4;
                #pragma unroll
                for (int q = 0; q < 4; q++) {
                    CPA16(XHa + bo + q * 16, (const uint4*)g_objh + rb + q);
                    CPA16(XLa + bo + q * 16, (const uint4*)g_objl + rb + q);
                }
            }
        } else {
            int hh = h - 2;
            u32 bo = (u32)(a * KP + 64 + hh * 32) * 2;
            if (L1) {
                float degf[6];
                #pragma unroll
                for (int s = 0; s < 6; s++)
                    degf[s] = (float)g_deg[s * MAX_OBJ + gc];
                #pragma unroll
                for (int q = 0; q < 8; q++) {
                    float v[4];
                    #pragma unroll
                    for (int t = 0; t < 4; t++) {
                        int cc = hh * 32 + q * 4 + t;
                        float s = 0.f;
                        #pragma unroll
                        for (int p = 0; p < 6; p++) s = fmaf(degf[p], cs[p * 64 + cc], s);
                        v[t] = s;
                    }
                    u32 h0, l0, h1, l1;
                    split2(v[0], v[1], h0, l0);
                    split2(v[2], v[3], h1, l1);
                    *(u64*)(xh_c + bo + q * 8) = (u64)h0 | ((u64)h1 << 32);
                    *(u64*)(xl_c + bo + q * 8) = (u64)l0 | ((u64)l1 << 32);
                }
            } else {
                const float* src = g_agg + (size_t)gc * HID + hh * 32;
                #pragma unroll
                for (int q = 0; q < 8; q++) {
                    float4 v = *(const float4*)(src + q * 4);
                    u32 h0, l0, h1, l1;
                    split2(v.x, v.y, h0, l0);
                    split2(v.z, v.w, h1, l1);
                    *(u64*)(xh_c + bo + q * 8) = (u64)h0 | ((u64)h1 << 32);
                    *(u64*)(xl_c + bo + q * 8) = (u64)l0 | ((u64)l1 << 32);
                }
            }
            // zero g_agg for next layer (owner row, after read)
            if (!L1 && go < nObj) {
                float4 z4 = make_float4(0.f, 0.f, 0.f, 0.f);
                float* dst = g_agg + (size_t)go * HID + hh * 32;
                #pragma unroll
                for (int q = 0; q < 8; q++) *(float4*)(dst + q * 4) = z4;
            }
        }
    }
    CPA_WAIT_ALL();
    __syncthreads();

    float acc[2 * 4 * 4];
    #pragma unroll
    for (int i = 0; i < 32; i++) acc[i] = 0.f;
    warp_gemm3<128, 128, 4>(XHa, XLa, U1H, U1L, mg, ng, lane, acc);
    __syncthreads();

    // epilogue1 -> H (both planes)
    #pragma unroll
    for (int mtl = 0; mtl < 2; mtl++)
        #pragma unroll
        for (int nt = 0; nt < 4; nt++) {
            float* d = acc + (mtl * 4 + nt) * 4;
            int row = mg * 32 + mtl * 16 + (lane >> 2);
            int col = ng * 32 + nt * 8 + 2 * (lane & 3);
            u32 hh, ll;
            float x0 = fmaxf(d[0] + b1s[col], 0.f), x1 = fmaxf(d[1] + b1s[col + 1], 0.f);
            split2(x0, x1, hh, ll);
            *(u32*)(xh_c + (row * KP + col) * 2) = hh;
            *(u32*)(xl_c + (row * KP + col) * 2) = ll;
            float x2 = fmaxf(d[2] + b1s[col], 0.f), x3 = fmaxf(d[3] + b1s[col + 1], 0.f);
            split2(x2, x3, hh, ll);
            *(u32*)(xh_c + ((row + 8) * KP + col) * 2) = hh;
            *(u32*)(xl_c + ((row + 8) * KP + col) * 2) = ll;
        }
    __syncthreads();

    #pragma unroll
    for (int i = 0; i < 16; i++) acc[i] = 0.f;
    warp_gemm3<128, 64, 4>(XHa, XLa, U2H, U2L, mg, ng, lane, acc);
    __syncthreads();

    // epilogue2 -> F (f32 [128][68])
    #pragma unroll
    for (int mtl = 0; mtl < 2; mtl++)
        #pragma unroll
        for (int nt = 0; nt < 2; nt++) {
            float* d = acc + (mtl * 2 + nt) * 4;
            int row = mg * 32 + mtl * 16 + (lane >> 2);
            int col = ng * 16 + nt * 8 + 2 * (lane & 3);
            *(float2*)(F + row * FP + col) =
                make_float2(d[0] + b2s[col], d[1] + b2s[col + 1]);
            *(float2*)(F + (row + 8) * FP + col) =
                make_float2(d[2] + b2s[col], d[3] + b2s[col + 1]);
        }
    __syncthreads();

    {   // write back: 4 threads/object, 16 cols each
        int a = tid >> 2, h = tid & 3;
        int go = base + a;
        if (go < nObj) {
            const float* f = F + a * FP + h * 16;
            float* dst = g_obj + (size_t)go * HID + h * 16;
            uint4 ph[2], pl[2];
            u32* phu = (u32*)ph; u32* plu = (u32*)pl;
            #pragma unroll
            for (int q = 0; q < 4; q++) {
                float4 v = *(const float4*)(f + q * 4);
                *(float4*)(dst + q * 4) = v;
                split2(v.x, v.y, phu[q * 2], plu[q * 2]);
                split2(v.z, v.w, phu[q * 2 + 1], plu[q * 2 + 1]);
            }
            uint4* dh = (uint4*)g_objh + (size_t)go * 8 + h * 2;
            uint4* dl = (uint4*)g_objl + (size_t)go * 8 + h * 2;
            dh[0] = ph[0]; dh[1] = ph[1];
            dl[0] = pl[0]; dl[1] = pl[1];
        }
    }
}

// ---------------------------------------------------------------------------
// small kernels
// ---------------------------------------------------------------------------
__global__ void zero_init_kernel(int nObj) {
    int i = blockIdx.x * 256 + threadIdx.x;
    if (i < 6 * MAX_OBJ)      g_deg[i] = 0;
    if (i < MAX_GRAPHS * HID) g_pooled[i] = 0.f;
    if (i < nObj * HID)       g_agg[i] = 0.f;
}
__global__ void pool_kernel(const int* __restrict__ batch, int nObj) {
    int c = threadIdx.x;
    int base = blockIdx.x * 64;
    int end = min(base + 64, nObj);
    int cur = -1; float s = 0.f;
    for (int o = base; o < end; o++) {
        int b = batch[o];
        if (b != cur) {
            if (cur >= 0) atomicAdd(&g_pooled[cur * HID + c], s);
            cur = b; s = 0.f;
        }
        s += g_obj[(size_t)o * HID + c];
    }
    if (cur >= 0) atomicAdd(&g_pooled[cur * HID + c], s);
}
__global__ void readout_kernel(const float* __restrict__ w1, const float* __restrict__ b1,
                               const float* __restrict__ w2, const float* __restrict__ b2,
                               float* __restrict__ out) {
    __shared__ float p[64];
    __shared__ float red[4];
    int g = blockIdx.x, t = threadIdx.x;
    if (t < 64) p[t] = g_pooled[g * HID + t];
    __syncthreads();
    float acc = 0.f;
    #pragma unroll
    for (int k = 0; k < 64; k++) acc = fmaf(p[k], w1[k * 128 + t], acc);
    acc = fmaxf(acc + b1[t], 0.f) * w2[t];
    #pragma unroll
    for (int off = 16; off; off >>= 1) acc += __shfl_down_sync(0xffffffffu, acc, off);
    if ((t & 31) == 0) red[t >> 5] = acc;
    __syncthreads();
    if (t == 0) out[g] = red[0] + red[1] + red[2] + red[3] + b2[0];
}

// ---------------------------------------------------------------------------
extern "C" void kernel_launch(void* const* d_in, const int* in_sizes, int n_in,
                              void* d_out, int out_size) {
    const float* w_p1_1 = (const float*)d_in[4];
    const float* b_p1_1 = (const float*)d_in[5];
    const float* w_p1_2 = (const float*)d_in[6];
    const float* b_p1_2 = (const float*)d_in[7];
    const float* w_p2_1 = (const float*)d_in[8];
    const float* b_p2_1 = (const float*)d_in[9];
    const float* w_p2_2 = (const float*)d_in[10];
    const float* b_p2_2 = (const float*)d_in[11];
    const float* w_p3_1 = (const float*)d_in[12];
    const float* b_p3_1 = (const float*)d_in[13];
    const float* w_p3_2 = (const float*)d_in[14];
    const float* b_p3_2 = (const float*)d_in[15];
    const float* w_u1   = (const float*)d_in[16];
    const float* b_u1   = (const float*)d_in[17];
    const float* w_u2   = (const float*)d_in[18];
    const float* b_u2   = (const float*)d_in[19];
    const float* w_r1   = (const float*)d_in[20];
    const float* b_r1   = (const float*)d_in[21];
    const float* w_r2   = (const float*)d_in[22];
    const float* b_r2   = (const float*)d_in[23];
    const int*   ei_p1  = (const int*)d_in[24];
    const int*   ei_p2  = (const int*)d_in[25];
    const int*   ei_p3  = (const int*)d_in[26];
    const int*   batch  = (const int*)d_in[27];

    const int nObj = in_sizes[0];
    const int nP1  = in_sizes[24];
    const int nP2  = in_sizes[25] / 2;
    const int nP3  = in_sizes[26] / 3;
    const int nGraphs = out_size;
    float* out = (float*)d_out;

    u16* wb = nullptr;
    cudaGetSymbolAddress((void**)&wb, g_wbuf);

    // smem: NWB*WB + 2*XB (X + F region) + biases + es
    const int smem1 = 4 * (64 * 72 * 2)   + 2 * (128 * 72 * 2)  + 8 * 64  + 1 * 128 * 4;
    const int smem2 = 4 * (128 * 136 * 2) + 2 * (128 * 136 * 2) + 8 * 128 + 2 * 128 * 4;
    const int smem3 = 2 * (192 * 200 * 2) + 2 * (64 * 200 * 2)  + 8 * 192 + 3 * 64 * 4;
    const int smemU = 2 * (128 * 136 * 2) + 2 * (64 * 136 * 2)
                    + 2 * (128 * 136 * 2) + 128 * 4 + 64 * 4 + 384 * 4;
    cudaFuncSetAttribute((pred_mma_kernel<1, 128, 2, true>), cudaFuncAttributeMaxDynamicSharedMemorySize, smem1);
    cudaFuncSetAttribute((pred_mma_kernel<2, 128, 1, true>), cudaFuncAttributeMaxDynamicSharedMemorySize, smem2);
    cudaFuncSetAttribute((pred_mma_kernel<3, 64, 1, false>), cudaFuncAttributeMaxDynamicSharedMemorySize, smem3);
    cudaFuncSetAttribute(update_mma_kernel<true>, cudaFuncAttributeMaxDynamicSharedMemorySize, smemU);
    cudaFuncSetAttribute(update_mma_kernel<false>, cudaFuncAttributeMaxDynamicSharedMemorySize, smemU);

    const int bObj = (nObj + 127) / 128;
    const int bP1  = (nP1 + 127) / 128;
    const int bP2  = (nP2 + 127) / 128;
    const int bP3  = (nP3 + 63) / 64;
    int nmax = nP1 > nP2 ? nP1 : nP2; if (nP3 > nmax) nmax = nP3;

    int zn = nObj * HID; if (6 * MAX_OBJ > zn) zn = 6 * MAX_OBJ;
    zero_init_kernel<<<(zn + 255) / 256, 256>>>(nObj);                        // 0
    prep_const_all<<<577, 256>>>(w_p1_1, w_p1_2, w_p2_1, w_p2_2,              // 1
                                 w_p3_1, w_p3_2, w_u1, w_u2,
                                 b_p1_1, b_p1_2, b_p2_1, b_p2_2, b_p3_1, b_p3_2);
    deg_all_kernel<<<dim3((nmax + 255) / 256, 6), 256>>>(ei_p1, nP1,          // 2
                                                         ei_p2, nP2,
                                                         ei_p3, nP3);
    update_mma_kernel<true><<<bObj, 512, smemU>>>(wb + 241664, wb + 259072,   // 3
                                                  wb + 276480, wb + 285184,
                                                  b_u1, b_u2, nObj);

    const bool fork = g_hx.ok;
    cudaStream_t sA = fork ? g_hx.s1 : (cudaStream_t)0;
    cudaStream_t sB = fork ? g_hx.s2 : (cudaStream_t)0;

    for (int layer = 1; layer < 3; layer++) {
        if (fork) {
            cudaEventRecord(g_hx.evA, 0);
            cudaStreamWaitEvent(sA, g_hx.evA, 0);
            cudaStreamWaitEvent(sB, g_hx.evA, 0);
        }
        pred_mma_kernel<1, 128, 2, true><<<bP1, 512, smem1, sA>>>(
            ei_p1, nP1, wb + 0, wb + 4608, wb + 9216, wb + 13824, b_p1_1, b_p1_2);
        pred_mma_kernel<2, 128, 1, true><<<bP2, 512, smem2, sB>>>(
            ei_p2, nP2, wb + 18432, wb + 35840, wb + 53248, wb + 70656, b_p2_1, b_p2_2);
        pred_mma_kernel<3, 64, 1, false><<<bP3, 512, smem3>>>(
            ei_p3, nP3, wb + 88064, wb + 126464, wb + 164864, wb + 203264, b_p3_1, b_p3_2);
        if (fork) {
            cudaEventRecord(g_hx.ev1, sA);
            cudaEventRecord(g_hx.ev2, sB);
            cudaStreamWaitEvent((cudaStream_t)0, g_hx.ev1, 0);
            cudaStreamWaitEvent((cudaStream_t)0, g_hx.ev2, 0);
        }
        update_mma_kernel<false><<<bObj, 512, smemU>>>(wb + 241664, wb + 259072,
                                                       wb + 276480, wb + 285184,
                                                       b_u1, b_u2, nObj);
    }

    pool_kernel<<<(nObj + 63) / 64, 64>>>(batch, nObj);
    readout_kernel<<<nGraphs, 128>>>(w_r1, b_r1, w_r2, b_r2, out);
}

// round 16
// speedup vs baseline: 1.4844x; 1.2006x over previous
#include <cuda_runtime.h>
#include <cuda_bf16.h>

#define HID 64
#define MAX_OBJ 100000
#define MAX_GRAPHS 256

typedef unsigned int u32;
typedef unsigned long long u64;
typedef unsigned short u16;

__device__ float g_obj[MAX_OBJ * HID];
__device__ float g_agg[MAX_OBJ * HID];
__device__ int   g_deg[6 * MAX_OBJ];
__device__ float g_const[64 + 128 + 192];
__device__ float g_pooled[MAX_GRAPHS * HID];

// pre-split bf16 planes of g_obj: row = 32 u32 = 8 uint4 (64 values)
__device__ __align__(16) u32 g_objh[MAX_OBJ * 32];
__device__ __align__(16) u32 g_objl[MAX_OBJ * 32];

// pre-transposed, bf16-split weights, layout [N][K+8] u16 per half.
__device__ __align__(16) u16 g_wbuf[293888];

// ---------------------------------------------------------------------------
struct HxStreams {
    cudaStream_t s1 = 0, s2 = 0;
    cudaEvent_t evA = 0, ev1 = 0, ev2 = 0;
    bool ok = false;
    HxStreams() {
        ok = (cudaStreamCreateWithFlags(&s1, cudaStreamNonBlocking) == cudaSuccess) &&
             (cudaStreamCreateWithFlags(&s2, cudaStreamNonBlocking) == cudaSuccess) &&
             (cudaEventCreateWithFlags(&evA, cudaEventDisableTiming) == cudaSuccess) &&
             (cudaEventCreateWithFlags(&ev1, cudaEventDisableTiming) == cudaSuccess) &&
             (cudaEventCreateWithFlags(&ev2, cudaEventDisableTiming) == cudaSuccess);
    }
};
static HxStreams g_hx;

// ---------------------------------------------------------------------------
__device__ __forceinline__ u32 s2u(const void* p) {
    u32 a;
    asm("{ .reg .u64 t; cvta.to.shared.u64 t, %1; cvt.u32.u64 %0, t; }"
        : "=r"(a) : "l"(p));
    return a;
}
__device__ __forceinline__ void split2(float x, float y, u32& h, u32& l) {
    __nv_bfloat162 hb = __float22bfloat162_rn(make_float2(x, y));
    u32 hu = *reinterpret_cast<u32*>(&hb);
    float xh = __uint_as_float(hu << 16);
    float yh = __uint_as_float(hu & 0xffff0000u);
    __nv_bfloat162 lb = __float22bfloat162_rn(make_float2(x - xh, y - yh));
    h = hu;
    l = *reinterpret_cast<u32*>(&lb);
}
__device__ __forceinline__ u32 pack_bf2(float x, float y) {
    __nv_bfloat162 hb = __float22bfloat162_rn(make_float2(x, y));
    return *reinterpret_cast<u32*>(&hb);
}

#define CPA16(dst_u32, src_ptr) \
    asm volatile("cp.async.cg.shared.global [%0], [%1], 16;" \
        :: "r"(dst_u32), "l"(src_ptr) : "memory")
#define CPA_WAIT_ALL() asm volatile("cp.async.wait_all;" ::: "memory")

#define LDSM4(r, addr) \
    asm volatile("ldmatrix.sync.aligned.m8n8.x4.shared.b16 {%0,%1,%2,%3}, [%4];" \
        : "=r"((r)[0]), "=r"((r)[1]), "=r"((r)[2]), "=r"((r)[3]) : "r"(addr))
#define LDSM2(r, addr) \
    asm volatile("ldmatrix.sync.aligned.m8n8.x2.shared.b16 {%0,%1}, [%2];" \
        : "=r"((r)[0]), "=r"((r)[1]) : "r"(addr))
#define MMA16816(d, a, b) \
    asm volatile("mma.sync.aligned.m16n8k16.row.col.f32.bf16.bf16.f32 " \
        "{%0,%1,%2,%3}, {%4,%5,%6,%7}, {%8,%9}, {%0,%1,%2,%3};" \
        : "+f"((d)[0]), "+f"((d)[1]), "+f"((d)[2]), "+f"((d)[3]) \
        : "r"((a)[0]), "r"((a)[1]), "r"((a)[2]), "r"((a)[3]), \
          "r"((b)[0]), "r"((b)[1]))

__device__ __forceinline__ void red4(float* p, float a, float b, float c, float d) {
    asm volatile("red.global.add.v4.f32 [%0], {%1, %2, %3, %4};"
                 :: "l"(p), "f"(a), "f"(b), "f"(c), "f"(d) : "memory");
}

// ---------------------------------------------------------------------------
// 3-pass split GEMM (A hi+lo, B hi+lo): update kernels (full precision).
// ---------------------------------------------------------------------------
template<int K, int N, int NG>
__device__ __forceinline__ void warp_gemm3(u32 xh, u32 xl, u32 wh, u32 wl,
                                           int mg, int ng, int lane, float* acc) {
    constexpr int KP  = K + 8;
    constexpr int NPW = N / NG;
    constexpr int NTW = NPW / 8;
    const u32 aoff = (u32)(((mg * 32 + (lane & 15)) * KP + (lane >> 4) * 8) * 2);
    const u32 boff = (u32)((((ng * NPW) + (lane & 7)) * KP + ((lane >> 3) & 1) * 8) * 2);
    #pragma unroll
    for (int kt = 0; kt < K / 16; kt++) {
        u32 A[2][2][4];
        #pragma unroll
        for (int mtl = 0; mtl < 2; mtl++) {
            u32 o = aoff + (u32)((mtl * 16 * KP + kt * 16) * 2);
            LDSM4(A[0][mtl], xh + o);
            LDSM4(A[1][mtl], xl + o);
        }
        #pragma unroll
        for (int nt = 0; nt < NTW; nt++) {
            u32 o = boff + (u32)((nt * 8 * KP + kt * 16) * 2);
            u32 Bh[2], Bl[2];
            LDSM2(Bh, wh + o);
            LDSM2(Bl, wl + o);
            #pragma unroll
            for (int mtl = 0; mtl < 2; mtl++) {
                float* d = acc + (mtl * NTW + nt) * 4;
                MMA16816(d, A[0][mtl], Bh);
                MMA16816(d, A[0][mtl], Bl);
                MMA16816(d, A[1][mtl], Bh);
            }
        }
    }
}

// ---------------------------------------------------------------------------
// 1-pass bf16 GEMM (A bf16, B bf16-hi): predicates.
// error ~2*1e-4 (A + B truncation, each ~1e-4 measured) — within 1e-3 gate
// ---------------------------------------------------------------------------
template<int K, int N, int NG>
__device__ __forceinline__ void warp_gemm1(u32 xh, u32 wh,
                                           int mg, int ng, int lane, float* acc) {
    constexpr int KP  = K + 8;
    constexpr int NPW = N / NG;
    constexpr int NTW = NPW / 8;
    const u32 aoff = (u32)(((mg * 32 + (lane & 15)) * KP + (lane >> 4) * 8) * 2);
    const u32 boff = (u32)((((ng * NPW) + (lane & 7)) * KP + ((lane >> 3) & 1) * 8) * 2);
    #pragma unroll
    for (int kt = 0; kt < K / 16; kt++) {
        u32 A[2][4];
        #pragma unroll
        for (int mtl = 0; mtl < 2; mtl++) {
            u32 o = aoff + (u32)((mtl * 16 * KP + kt * 16) * 2);
            LDSM4(A[mtl], xh + o);
        }
        #pragma unroll
        for (int nt = 0; nt < NTW; nt++) {
            u32 o = boff + (u32)((nt * 8 * KP + kt * 16) * 2);
            u32 Bh[2];
            LDSM2(Bh, wh + o);
            #pragma unroll
            for (int mtl = 0; mtl < 2; mtl++)
                MMA16816(acc + (mtl * NTW + nt) * 4, A[mtl], Bh);
        }
    }
}

// ---------------------------------------------------------------------------
// merged weight prep + const precompute
// ---------------------------------------------------------------------------
__global__ void prep_const_all(const float* __restrict__ w0, const float* __restrict__ w1,
                               const float* __restrict__ w2, const float* __restrict__ w3,
                               const float* __restrict__ w4, const float* __restrict__ w5,
                               const float* __restrict__ w6, const float* __restrict__ w7,
                               const float* __restrict__ b11, const float* __restrict__ b12,
                               const float* __restrict__ b21, const float* __restrict__ b22,
                               const float* __restrict__ b31, const float* __restrict__ b32) {
    int b = blockIdx.x;
    if (b >= 574) {
        int pred = b - 574, j = threadIdx.x;
        const float *b1, *W2, *b2; int D, off;
        if (pred == 0)      { b1 = b11; W2 = w1; b2 = b12; D = 64;  off = 0;   }
        else if (pred == 1) { b1 = b21; W2 = w3; b2 = b22; D = 128; off = 64;  }
        else                { b1 = b31; W2 = w5; b2 = b32; D = 192; off = 192; }
        if (j < D) {
            float s = 0.f;
            for (int k = 0; k < D; k++) s = fmaf(fmaxf(b1[k], 0.f), W2[k * D + j], s);
            g_const[off + j] = s + b2[j];
        }
        return;
    }
    const float* W; int K, N, oh, ol, b0;
    if      (b < 18)  { W = w0; K = 64;  N = 64;  oh = 0;      ol = 4608;   b0 = 0;   }
    else if (b < 36)  { W = w1; K = 64;  N = 64;  oh = 9216;   ol = 13824;  b0 = 18;  }
    else if (b < 104) { W = w2; K = 128; N = 128; oh = 18432;  ol = 35840;  b0 = 36;  }
    else if (b < 172) { W = w3; K = 128; N = 128; oh = 53248;  ol = 70656;  b0 = 104; }
    else if (b < 322) { W = w4; K = 192; N = 192; oh = 88064;  ol = 126464; b0 = 172; }
    else if (b < 472) { W = w5; K = 192; N = 192; oh = 164864; ol = 203264; b0 = 322; }
    else if (b < 540) { W = w6; K = 128; N = 128; oh = 241664; ol = 259072; b0 = 472; }
    else              { W = w7; K = 128; N = 64;  oh = 276480; ol = 285184; b0 = 540; }
    int i = (b - b0) * 256 + threadIdx.x;
    int KP = K + 8;
    if (i >= N * KP) return;
    int n = i / KP, k = i - n * KP;
    u16 hv = 0, lv = 0;
    if (k < K) {
        float v = W[k * N + n];
        __nv_bfloat16 h = __float2bfloat16(v);
        __nv_bfloat16 l = __float2bfloat16(v - __bfloat162float(h));
        hv = *reinterpret_cast<u16*>(&h);
        lv = *reinterpret_cast<u16*>(&l);
    }
    g_wbuf[oh + i] = hv;
    g_wbuf[ol + i] = lv;
}

__global__ void deg_all_kernel(const int* __restrict__ ei1, int n1,
                               const int* __restrict__ ei2, int n2,
                               const int* __restrict__ ei3, int n3) {
    int s = blockIdx.y;
    int i = blockIdx.x * 256 + threadIdx.x;
    const int* e; int n, row;
    if (s == 0)     { e = ei1; n = n1; row = 0; }
    else if (s < 3) { e = ei2; n = n2; row = s - 1; }
    else            { e = ei3; n = n3; row = s - 3; }
    if (i < n) atomicAdd(&g_deg[s * MAX_OBJ + e[row * n + i]], 1);
}

// ---------------------------------------------------------------------------
// fused predicate kernel: single-plane A AND B (1-pass GEMMs).
// BOTH: stage W1h+W2h up-front; else stage W2h overlapped with epilogue1.
// ---------------------------------------------------------------------------
template<int R, int ROWS, int MAXB, bool BOTH>
__global__ void __launch_bounds__(512, MAXB)
pred_mma_kernel(const int* __restrict__ ei, int nAtoms,
                const u16* __restrict__ W1h, const u16* __restrict__ W2h,
                const float* __restrict__ b1, const float* __restrict__ b2) {
    constexpr int D   = 64 * R;
    constexpr int KP  = D + 8;
    constexpr int NG  = 16 / (ROWS / 32);
    constexpr int NPW = D / NG;
    constexpr int NTW = NPW / 8;
    constexpr int TPA = 512 / ROWS;
    constexpr int U4  = 8 / TPA;
    constexpr int WB  = D * KP * 2;        // bytes per weight plane
    constexpr int XB  = ROWS * KP * 2;     // one X plane; region is 2*XB (X + F)
    constexpr int FP  = D + 4;
    constexpr int NWB = BOTH ? 2 : 1;

    extern __shared__ char sm[];
    const u32 su = s2u(sm);
    const u32 W1H = su;
    const u32 W2H = BOTH ? su + WB : su;
    const u32 XHa = su + NWB * WB;
    char* xh_c = sm + NWB * WB;
    float* b1s = (float*)(sm + NWB * WB + 2 * XB);
    float* b2s = b1s + D;
    int*   es  = (int*)(b2s + D);
    float* F   = (float*)(sm + NWB * WB);   // overlays X region (2*XB >= F)

    const int tid = threadIdx.x, warp = tid >> 5, lane = tid & 31;
    const int ng = warp % NG, mg = warp / NG;
    const int base = blockIdx.x * ROWS;

    for (int i = tid * 16; i < WB; i += 512 * 16) {
        CPA16(W1H + i, (const char*)W1h + i);
        if (BOTH) CPA16(W2H + i, (const char*)W2h + i);
    }
    for (int i = tid; i < D; i += 512) { b1s[i] = b1[i]; b2s[i] = b2[i]; }
    if (tid < R * ROWS) {
        int s = tid / ROWS, a = tid % ROWS;
        int ga = base + a;
        es[tid] = (ga < nAtoms) ? ei[s * nAtoms + ga] : 0;
    }
    __syncthreads();   // es visible

    {   // gather hi plane only
        int a = tid / TPA, h = tid % TPA;
        #pragma unroll
        for (int s = 0; s < R; s++) {
            size_t rb = (size_t)es[s * ROWS + a] * 8 + h * U4;
            u32 bo = (u32)(a * KP + s * 64 + h * (64 / TPA)) * 2;
            #pragma unroll
            for (int q = 0; q < U4; q++)
                CPA16(XHa + bo + q * 16, (const uint4*)g_objh + rb + q);
        }
    }
    CPA_WAIT_ALL();
    __syncthreads();

    float acc[2 * NTW * 4];
    #pragma unroll
    for (int i = 0; i < 2 * NTW * 4; i++) acc[i] = 0.f;
    warp_gemm1<D, D, NG>(XHa, W1H, mg, ng, lane, acc);
    __syncthreads();

    if (!BOTH) {
        for (int i = tid * 16; i < WB; i += 512 * 16)
            CPA16(W2H + i, (const char*)W2h + i);
    }
    // epilogue1: H = relu(C + b1) -> hi plane only
    #pragma unroll
    for (int mtl = 0; mtl < 2; mtl++)
        #pragma unroll
        for (int nt = 0; nt < NTW; nt++) {
            float* d = acc + (mtl * NTW + nt) * 4;
            int row = mg * 32 + mtl * 16 + (lane >> 2);
            int col = ng * NPW + nt * 8 + 2 * (lane & 3);
            float x0 = fmaxf(d[0] + b1s[col], 0.f), x1 = fmaxf(d[1] + b1s[col + 1], 0.f);
            *(u32*)(xh_c + (row * KP + col) * 2) = pack_bf2(x0, x1);
            float x2 = fmaxf(d[2] + b1s[col], 0.f), x3 = fmaxf(d[3] + b1s[col + 1], 0.f);
            *(u32*)(xh_c + ((row + 8) * KP + col) * 2) = pack_bf2(x2, x3);
        }
    if (!BOTH) CPA_WAIT_ALL();
    __syncthreads();

    #pragma unroll
    for (int i = 0; i < 2 * NTW * 4; i++) acc[i] = 0.f;
    warp_gemm1<D, D, NG>(XHa, W2H, mg, ng, lane, acc);
    __syncthreads();

    // epilogue2: C + b2 -> F
    #pragma unroll
    for (int mtl = 0; mtl < 2; mtl++)
        #pragma unroll
        for (int nt = 0; nt < NTW; nt++) {
            float* d = acc + (mtl * NTW + nt) * 4;
            int row = mg * 32 + mtl * 16 + (lane >> 2);
            int col = ng * NPW + nt * 8 + 2 * (lane & 3);
            *(float2*)(F + row * FP + col) =
                make_float2(d[0] + b2s[col], d[1] + b2s[col + 1]);
            *(float2*)(F + (row + 8) * FP + col) =
                make_float2(d[2] + b2s[col], d[3] + b2s[col + 1]);
        }
    __syncthreads();

    // scatter
    {
        int a = tid % ROWS, part = tid / ROWS;
        if (base + a < nAtoms) {
            #pragma unroll
            for (int j = part * (D / TPA); j < part * (D / TPA) + D / TPA; j += 4) {
                float* dst = g_agg + (size_t)es[(j >> 6) * ROWS + a] * HID + (j & 63);
                const float* f = F + a * FP + j;
                red4(dst, f[0], f[1], f[2], f[3]);
            }
        }
    }
}

// ---------------------------------------------------------------------------
// object update: 128 objects/block, 512 threads, 4Mx4N, 3-pass (full precision)
// ---------------------------------------------------------------------------
template<bool L1>
__global__ void __launch_bounds__(512, 1)
update_mma_kernel(const u16* __restrict__ U1h, const u16* __restrict__ U1l,
                  const u16* __restrict__ U2h, const u16* __restrict__ U2l,
                  const float* __restrict__ bu1, const float* __restrict__ bu2,
                  int nObj) {
    constexpr int KP  = 136;
    constexpr int WB1 = 128 * KP * 2;
    constexpr int WB2 = 64 * KP * 2;
    constexpr int XB  = 128 * KP * 2;
    constexpr int FP  = 68;

    extern __shared__ char sm[];
    const u32 su = s2u(sm);
    const u32 U1H = su, U1L = su + WB1;
    const u32 U2H = su + 2 * WB1, U2L = su + 2 * WB1 + WB2;
    const u32 XHa = su + 2 * WB1 + 2 * WB2, XLa = XHa + XB;
    char* xh_c = sm + 2 * WB1 + 2 * WB2;
    char* xl_c = xh_c + XB;
    float* b1s = (float*)(xh_c + 2 * XB);
    float* b2s = b1s + 128;
    float* cs  = b2s + 64;
    float* F   = (float*)xh_c;

    const int tid = threadIdx.x, warp = tid >> 5, lane = tid & 31;
    const int ng = warp & 3, mg = warp >> 2;
    const int base = blockIdx.x * 128;

    for (int i = tid * 16; i < WB1; i += 512 * 16) {
        CPA16(U1H + i, (const char*)U1h + i);
        CPA16(U1L + i, (const char*)U1l + i);
    }
    for (int i = tid * 16; i < WB2; i += 512 * 16) {
        CPA16(U2H + i, (const char*)U2h + i);
        CPA16(U2L + i, (const char*)U2l + i);
    }
    if (tid < 128) b1s[tid] = bu1[tid];
    else if (tid < 192) b2s[tid - 128] = bu2[tid - 128];
    if (L1) { for (int i = tid; i < 384; i += 512) cs[i] = g_const[i]; }
    if (L1) __syncthreads();

    {   // gather cat(obj, agg): 4 threads per object
        int a = tid >> 2, h = tid & 3;
        int go = base + a;
        int gc = (go < nObj) ? go : 0;
        if (h < 2) {
            u32 bo = (u32)(a * KP + h * 32) * 2;
            if (L1) {
                uint4 z = make_uint4(0, 0, 0, 0);
                #pragma unroll
                for (int q = 0; q < 4; q++) {
                    *(uint4*)(xh_c + bo + q * 16) = z;
                    *(uint4*)(xl_c + bo + q * 16) = z;
                }
            } else {
                size_t rb = (size_t)gc * 8 + h * 4;
                #pragma unroll
                for (int q = 0; q < 4; q++) {
                    CPA16(XHa + bo + q * 16, (const uint4*)g_objh + rb + q);
                    CPA16(XLa + bo + q * 16, (const uint4*)g_objl + rb + q);
                }
            }
        } else {
            int hh = h - 2;
            u32 bo = (u32)(a * KP + 64 + hh * 32) * 2;
            if (L1) {
                float degf[6];
                #pragma unroll
                for (int s = 0; s < 6; s++)
                    degf[s] = (float)g_deg[s * MAX_OBJ + gc];
                #pragma unroll
                for (int q = 0; q < 8; q++) {
                    float v[4];
                    #pragma unroll
                    for (int t = 0; t < 4; t++) {
                        int cc = hh * 32 + q * 4 + t;
                        float s = 0.f;
                        #pragma unroll
                        for (int p = 0; p < 6; p++) s = fmaf(degf[p], cs[p * 64 + cc], s);
                        v[t] = s;
                    }
                    u32 h0, l0, h1, l1;
                    split2(v[0], v[1], h0, l0);
                    split2(v[2], v[3], h1, l1);
                    *(u64*)(xh_c + bo + q * 8) = (u64)h0 | ((u64)h1 << 32);
                    *(u64*)(xl_c + bo + q * 8) = (u64)l0 | ((u64)l1 << 32);
                }
            } else {
                const float* src = g_agg + (size_t)gc * HID + hh * 32;
                #pragma unroll
                for (int q = 0; q < 8; q++) {
                    float4 v = *(const float4*)(src + q * 4);
                    u32 h0, l0, h1, l1;
                    split2(v.x, v.y, h0, l0);
                    split2(v.z, v.w, h1, l1);
                    *(u64*)(xh_c + bo + q * 8) = (u64)h0 | ((u64)h1 << 32);
                    *(u64*)(xl_c + bo + q * 8) = (u64)l0 | ((u64)l1 << 32);
                }
            }
            // zero g_agg for next layer (owner row, after read)
            if (!L1 && go < nObj) {
                float4 z4 = make_float4(0.f, 0.f, 0.f, 0.f);
                float* dst = g_agg + (size_t)go * HID + hh * 32;
                #pragma unroll
                for (int q = 0; q < 8; q++) *(float4*)(dst + q * 4) = z4;
            }
        }
    }
    CPA_WAIT_ALL();
    __syncthreads();

    float acc[2 * 4 * 4];
    #pragma unroll
    for (int i = 0; i < 32; i++) acc[i] = 0.f;
    warp_gemm3<128, 128, 4>(XHa, XLa, U1H, U1L, mg, ng, lane, acc);
    __syncthreads();

    // epilogue1 -> H (both planes)
    #pragma unroll
    for (int mtl = 0; mtl < 2; mtl++)
        #pragma unroll
        for (int nt = 0; nt < 4; nt++) {
            float* d = acc + (mtl * 4 + nt) * 4;
            int row = mg * 32 + mtl * 16 + (lane >> 2);
            int col = ng * 32 + nt * 8 + 2 * (lane & 3);
            u32 hh, ll;
            float x0 = fmaxf(d[0] + b1s[col], 0.f), x1 = fmaxf(d[1] + b1s[col + 1], 0.f);
            split2(x0, x1, hh, ll);
            *(u32*)(xh_c + (row * KP + col) * 2) = hh;
            *(u32*)(xl_c + (row * KP + col) * 2) = ll;
            float x2 = fmaxf(d[2] + b1s[col], 0.f), x3 = fmaxf(d[3] + b1s[col + 1], 0.f);
            split2(x2, x3, hh, ll);
            *(u32*)(xh_c + ((row + 8) * KP + col) * 2) = hh;
            *(u32*)(xl_c + ((row + 8) * KP + col) * 2) = ll;
        }
    __syncthreads();

    #pragma unroll
    for (int i = 0; i < 16; i++) acc[i] = 0.f;
    warp_gemm3<128, 64, 4>(XHa, XLa, U2H, U2L, mg, ng, lane, acc);
    __syncthreads();

    // epilogue2 -> F (f32 [128][68])
    #pragma unroll
    for (int mtl = 0; mtl < 2; mtl++)
        #pragma unroll
        for (int nt = 0; nt < 2; nt++) {
            float* d = acc + (mtl * 2 + nt) * 4;
            int row = mg * 32 + mtl * 16 + (lane >> 2);
            int col = ng * 16 + nt * 8 + 2 * (lane & 3);
            *(float2*)(F + row * FP + col) =
                make_float2(d[0] + b2s[col], d[1] + b2s[col + 1]);
            *(float2*)(F + (row + 8) * FP + col) =
                make_float2(d[2] + b2s[col], d[3] + b2s[col + 1]);
        }
    __syncthreads();

    {   // write back: 4 threads/object, 16 cols each
        int a = tid >> 2, h = tid & 3;
        int go = base + a;
        if (go < nObj) {
            const float* f = F + a * FP + h * 16;
            float* dst = g_obj + (size_t)go * HID + h * 16;
            uint4 ph[2], pl[2];
            u32* phu = (u32*)ph; u32* plu = (u32*)pl;
            #pragma unroll
            for (int q = 0; q < 4; q++) {
                float4 v = *(const float4*)(f + q * 4);
                *(float4*)(dst + q * 4) = v;
                split2(v.x, v.y, phu[q * 2], plu[q * 2]);
                split2(v.z, v.w, phu[q * 2 + 1], plu[q * 2 + 1]);
            }
            uint4* dh = (uint4*)g_objh + (size_t)go * 8 + h * 2;
            uint4* dl = (uint4*)g_objl + (size_t)go * 8 + h * 2;
            dh[0] = ph[0]; dh[1] = ph[1];
            dl[0] = pl[0]; dl[1] = pl[1];
        }
    }
}

// ---------------------------------------------------------------------------
// small kernels
// ---------------------------------------------------------------------------
__global__ void zero_init_kernel(int nObj) {
    int i = blockIdx.x * 256 + threadIdx.x;
    if (i < 6 * MAX_OBJ)      g_deg[i] = 0;
    if (i < MAX_GRAPHS * HID) g_pooled[i] = 0.f;
    if (i < nObj * HID)       g_agg[i] = 0.f;
}
__global__ void pool_kernel(const int* __restrict__ batch, int nObj) {
    int c = threadIdx.x;
    int base = blockIdx.x * 64;
    int end = min(base + 64, nObj);
    int cur = -1; float s = 0.f;
    for (int o = base; o < end; o++) {
        int b = batch[o];
        if (b != cur) {
            if (cur >= 0) atomicAdd(&g_pooled[cur * HID + c], s);
            cur = b; s = 0.f;
        }
        s += g_obj[(size_t)o * HID + c];
    }
    if (cur >= 0) atomicAdd(&g_pooled[cur * HID + c], s);
}
__global__ void readout_kernel(const float* __restrict__ w1, const float* __restrict__ b1,
                               const float* __restrict__ w2, const float* __restrict__ b2,
                               float* __restrict__ out) {
    __shared__ float p[64];
    __shared__ float red[4];
    int g = blockIdx.x, t = threadIdx.x;
    if (t < 64) p[t] = g_pooled[g * HID + t];
    __syncthreads();
    float acc = 0.f;
    #pragma unroll
    for (int k = 0; k < 64; k++) acc = fmaf(p[k], w1[k * 128 + t], acc);
    acc = fmaxf(acc + b1[t], 0.f) * w2[t];
    #pragma unroll
    for (int off = 16; off; off >>= 1) acc += __shfl_down_sync(0xffffffffu, acc, off);
    if ((t & 31) == 0) red[t >> 5] = acc;
    __syncthreads();
    if (t == 0) out[g] = red[0] + red[1] + red[2] + red[3] + b2[0];
}

// ---------------------------------------------------------------------------
extern "C" void kernel_launch(void* const* d_in, const int* in_sizes, int n_in,
                              void* d_out, int out_size) {
    const float* w_p1_1 = (const float*)d_in[4];
    const float* b_p1_1 = (const float*)d_in[5];
    const float* w_p1_2 = (const float*)d_in[6];
    const float* b_p1_2 = (const float*)d_in[7];
    const float* w_p2_1 = (const float*)d_in[8];
    const float* b_p2_1 = (const float*)d_in[9];
    const float* w_p2_2 = (const float*)d_in[10];
    const float* b_p2_2 = (const float*)d_in[11];
    const float* w_p3_1 = (const float*)d_in[12];
    const float* b_p3_1 = (const float*)d_in[13];
    const float* w_p3_2 = (const float*)d_in[14];
    const float* b_p3_2 = (const float*)d_in[15];
    const float* w_u1   = (const float*)d_in[16];
    const float* b_u1   = (const float*)d_in[17];
    const float* w_u2   = (const float*)d_in[18];
    const float* b_u2   = (const float*)d_in[19];
    const float* w_r1   = (const float*)d_in[20];
    const float* b_r1   = (const float*)d_in[21];
    const float* w_r2   = (const float*)d_in[22];
    const float* b_r2   = (const float*)d_in[23];
    const int*   ei_p1  = (const int*)d_in[24];
    const int*   ei_p2  = (const int*)d_in[25];
    const int*   ei_p3  = (const int*)d_in[26];
    const int*   batch  = (const int*)d_in[27];

    const int nObj = in_sizes[0];
    const int nP1  = in_sizes[24];
    const int nP2  = in_sizes[25] / 2;
    const int nP3  = in_sizes[26] / 3;
    const int nGraphs = out_size;
    float* out = (float*)d_out;

    u16* wb = nullptr;
    cudaGetSymbolAddress((void**)&wb, g_wbuf);

    // smem: NWB*WB + 2*XB (X + F region) + biases + es
    const int smem1 = 2 * (64 * 72 * 2)   + 2 * (128 * 72 * 2)  + 8 * 64  + 1 * 128 * 4;
    const int smem2 = 2 * (128 * 136 * 2) + 2 * (128 * 136 * 2) + 8 * 128 + 2 * 128 * 4;
    const int smem3 = 1 * (192 * 200 * 2) + 2 * (64 * 200 * 2)  + 8 * 192 + 3 * 64 * 4;
    const int smemU = 2 * (128 * 136 * 2) + 2 * (64 * 136 * 2)
                    + 2 * (128 * 136 * 2) + 128 * 4 + 64 * 4 + 384 * 4;
    cudaFuncSetAttribute((pred_mma_kernel<1, 128, 2, true>), cudaFuncAttributeMaxDynamicSharedMemorySize, smem1);
    cudaFuncSetAttribute((pred_mma_kernel<2, 128, 1, true>), cudaFuncAttributeMaxDynamicSharedMemorySize, smem2);
    cudaFuncSetAttribute((pred_mma_kernel<3, 64, 1, false>), cudaFuncAttributeMaxDynamicSharedMemorySize, smem3);
    cudaFuncSetAttribute(update_mma_kernel<true>, cudaFuncAttributeMaxDynamicSharedMemorySize, smemU);
    cudaFuncSetAttribute(update_mma_kernel<false>, cudaFuncAttributeMaxDynamicSharedMemorySize, smemU);

    const int bObj = (nObj + 127) / 128;
    const int bP1  = (nP1 + 127) / 128;
    const int bP2  = (nP2 + 127) / 128;
    const int bP3  = (nP3 + 63) / 64;
    int nmax = nP1 > nP2 ? nP1 : nP2; if (nP3 > nmax) nmax = nP3;

    int zn = nObj * HID; if (6 * MAX_OBJ > zn) zn = 6 * MAX_OBJ;
    zero_init_kernel<<<(zn + 255) / 256, 256>>>(nObj);                        // 0
    prep_const_all<<<577, 256>>>(w_p1_1, w_p1_2, w_p2_1, w_p2_2,              // 1
                                 w_p3_1, w_p3_2, w_u1, w_u2,
                                 b_p1_1, b_p1_2, b_p2_1, b_p2_2, b_p3_1, b_p3_2);
    deg_all_kernel<<<dim3((nmax + 255) / 256, 6), 256>>>(ei_p1, nP1,          // 2
                                                         ei_p2, nP2,
                                                         ei_p3, nP3);
    update_mma_kernel<true><<<bObj, 512, smemU>>>(wb + 241664, wb + 259072,   // 3
                                                  wb + 276480, wb + 285184,
                                                  b_u1, b_u2, nObj);

    const bool fork = g_hx.ok;
    cudaStream_t sA = fork ? g_hx.s1 : (cudaStream_t)0;
    cudaStream_t sB = fork ? g_hx.s2 : (cudaStream_t)0;

    for (int layer = 1; layer < 3; layer++) {
        if (fork) {
            cudaEventRecord(g_hx.evA, 0);
            cudaStreamWaitEvent(sA, g_hx.evA, 0);
            cudaStreamWaitEvent(sB, g_hx.evA, 0);
        }
        pred_mma_kernel<1, 128, 2, true><<<bP1, 512, smem1, sA>>>(
            ei_p1, nP1, wb + 0, wb + 9216, b_p1_1, b_p1_2);
        pred_mma_kernel<2, 128, 1, true><<<bP2, 512, smem2, sB>>>(
            ei_p2, nP2, wb + 18432, wb + 53248, b_p2_1, b_p2_2);
        pred_mma_kernel<3, 64, 1, false><<<bP3, 512, smem3>>>(
            ei_p3, nP3, wb + 88064, wb + 164864, b_p3_1, b_p3_2);
        if (fork) {
            cudaEventRecord(g_hx.ev1, sA);
            cudaEventRecord(g_hx.ev2, sB);
            cudaStreamWaitEvent((cudaStream_t)0, g_hx.ev1, 0);
            cudaStreamWaitEvent((cudaStream_t)0, g_hx.ev2, 0);
        }
        update_mma_kernel<false><<<bObj, 512, smemU>>>(wb + 241664, wb + 259072,
                                                       wb + 276480, wb + 285184,
                                                       b_u1, b_u2, nObj);
    }

    pool_kernel<<<(nObj + 63) / 64, 64>>>(batch, nObj);
    readout_kernel<<<nGraphs, 128>>>(w_r1, b_r1, w_r2, b_r2, out);
}

// round 17
// speedup vs baseline: 1.5346x; 1.0338x over previous
#include <cuda_runtime.h>
#include <cuda_bf16.h>

#define HID 64
#define MAX_OBJ 100000
#define MAX_GRAPHS 256

typedef unsigned int u32;
typedef unsigned long long u64;
typedef unsigned short u16;

__device__ float g_obj[MAX_OBJ * HID];
__device__ float g_agg[MAX_OBJ * HID];
__device__ int   g_deg[6 * MAX_OBJ];
__device__ float g_const[64 + 128 + 192];
__device__ float g_pooled[MAX_GRAPHS * HID];

// pre-split bf16 planes of g_obj: row = 32 u32 = 8 uint4 (64 values)
__device__ __align__(16) u32 g_objh[MAX_OBJ * 32];
__device__ __align__(16) u32 g_objl[MAX_OBJ * 32];

// pre-transposed, bf16-split weights, layout [N][K+8] u16 per half.
__device__ __align__(16) u16 g_wbuf[293888];

// ---------------------------------------------------------------------------
struct HxStreams {
    cudaStream_t s1 = 0, s2 = 0;
    cudaEvent_t evA = 0, ev1 = 0, ev2 = 0;
    bool ok = false;
    HxStreams() {
        ok = (cudaStreamCreateWithFlags(&s1, cudaStreamNonBlocking) == cudaSuccess) &&
             (cudaStreamCreateWithFlags(&s2, cudaStreamNonBlocking) == cudaSuccess) &&
             (cudaEventCreateWithFlags(&evA, cudaEventDisableTiming) == cudaSuccess) &&
             (cudaEventCreateWithFlags(&ev1, cudaEventDisableTiming) == cudaSuccess) &&
             (cudaEventCreateWithFlags(&ev2, cudaEventDisableTiming) == cudaSuccess);
    }
};
static HxStreams g_hx;

// ---------------------------------------------------------------------------
__device__ __forceinline__ u32 s2u(const void* p) {
    u32 a;
    asm("{ .reg .u64 t; cvta.to.shared.u64 t, %1; cvt.u32.u64 %0, t; }"
        : "=r"(a) : "l"(p));
    return a;
}
__device__ __forceinline__ void split2(float x, float y, u32& h, u32& l) {
    __nv_bfloat162 hb = __float22bfloat162_rn(make_float2(x, y));
    u32 hu = *reinterpret_cast<u32*>(&hb);
    float xh = __uint_as_float(hu << 16);
    float yh = __uint_as_float(hu & 0xffff0000u);
    __nv_bfloat162 lb = __float22bfloat162_rn(make_float2(x - xh, y - yh));
    h = hu;
    l = *reinterpret_cast<u32*>(&lb);
}
__device__ __forceinline__ u32 pack_bf2(float x, float y) {
    __nv_bfloat162 hb = __float22bfloat162_rn(make_float2(x, y));
    return *reinterpret_cast<u32*>(&hb);
}

#define CPA16(dst_u32, src_ptr) \
    asm volatile("cp.async.cg.shared.global [%0], [%1], 16;" \
        :: "r"(dst_u32), "l"(src_ptr) : "memory")
#define CPA_WAIT_ALL() asm volatile("cp.async.wait_all;" ::: "memory")

#define LDSM4(r, addr) \
    asm volatile("ldmatrix.sync.aligned.m8n8.x4.shared.b16 {%0,%1,%2,%3}, [%4];" \
        : "=r"((r)[0]), "=r"((r)[1]), "=r"((r)[2]), "=r"((r)[3]) : "r"(addr))
#define LDSM2(r, addr) \
    asm volatile("ldmatrix.sync.aligned.m8n8.x2.shared.b16 {%0,%1}, [%2];" \
        : "=r"((r)[0]), "=r"((r)[1]) : "r"(addr))
#define MMA16816(d, a, b) \
    asm volatile("mma.sync.aligned.m16n8k16.row.col.f32.bf16.bf16.f32 " \
        "{%0,%1,%2,%3}, {%4,%5,%6,%7}, {%8,%9}, {%0,%1,%2,%3};" \
        : "+f"((d)[0]), "+f"((d)[1]), "+f"((d)[2]), "+f"((d)[3]) \
        : "r"((a)[0]), "r"((a)[1]), "r"((a)[2]), "r"((a)[3]), \
          "r"((b)[0]), "r"((b)[1]))

__device__ __forceinline__ void red4(float* p, float a, float b, float c, float d) {
    asm volatile("red.global.add.v4.f32 [%0], {%1, %2, %3, %4};"
                 :: "l"(p), "f"(a), "f"(b), "f"(c), "f"(d) : "memory");
}

// ---------------------------------------------------------------------------
// 3-pass split GEMM (A hi+lo, B hi+lo): update kernels (full precision).
// ---------------------------------------------------------------------------
template<int K, int N, int NG>
__device__ __forceinline__ void warp_gemm3(u32 xh, u32 xl, u32 wh, u32 wl,
                                           int mg, int ng, int lane, float* acc) {
    constexpr int KP  = K + 8;
    constexpr int NPW = N / NG;
    constexpr int NTW = NPW / 8;
    const u32 aoff = (u32)(((mg * 32 + (lane & 15)) * KP + (lane >> 4) * 8) * 2);
    const u32 boff = (u32)((((ng * NPW) + (lane & 7)) * KP + ((lane >> 3) & 1) * 8) * 2);
    #pragma unroll
    for (int kt = 0; kt < K / 16; kt++) {
        u32 A[2][2][4];
        #pragma unroll
        for (int mtl = 0; mtl < 2; mtl++) {
            u32 o = aoff + (u32)((mtl * 16 * KP + kt * 16) * 2);
            LDSM4(A[0][mtl], xh + o);
            LDSM4(A[1][mtl], xl + o);
        }
        #pragma unroll
        for (int nt = 0; nt < NTW; nt++) {
            u32 o = boff + (u32)((nt * 8 * KP + kt * 16) * 2);
            u32 Bh[2], Bl[2];
            LDSM2(Bh, wh + o);
            LDSM2(Bl, wl + o);
            #pragma unroll
            for (int mtl = 0; mtl < 2; mtl++) {
                float* d = acc + (mtl * NTW + nt) * 4;
                MMA16816(d, A[0][mtl], Bh);
                MMA16816(d, A[0][mtl], Bl);
                MMA16816(d, A[1][mtl], Bh);
            }
        }
    }
}

// ---------------------------------------------------------------------------
// 1-pass bf16 GEMM (A bf16, B bf16-hi): predicates.
// ---------------------------------------------------------------------------
template<int K, int N, int NG>
__device__ __forceinline__ void warp_gemm1(u32 xh, u32 wh,
                                           int mg, int ng, int lane, float* acc) {
    constexpr int KP  = K + 8;
    constexpr int NPW = N / NG;
    constexpr int NTW = NPW / 8;
    const u32 aoff = (u32)(((mg * 32 + (lane & 15)) * KP + (lane >> 4) * 8) * 2);
    const u32 boff = (u32)((((ng * NPW) + (lane & 7)) * KP + ((lane >> 3) & 1) * 8) * 2);
    #pragma unroll
    for (int kt = 0; kt < K / 16; kt++) {
        u32 A[2][4];
        #pragma unroll
        for (int mtl = 0; mtl < 2; mtl++) {
            u32 o = aoff + (u32)((mtl * 16 * KP + kt * 16) * 2);
            LDSM4(A[mtl], xh + o);
        }
        #pragma unroll
        for (int nt = 0; nt < NTW; nt++) {
            u32 o = boff + (u32)((nt * 8 * KP + kt * 16) * 2);
            u32 Bh[2];
            LDSM2(Bh, wh + o);
            #pragma unroll
            for (int mtl = 0; mtl < 2; mtl++)
                MMA16816(acc + (mtl * NTW + nt) * 4, A[mtl], Bh);
        }
    }
}

// ---------------------------------------------------------------------------
// merged weight prep + const precompute
// ---------------------------------------------------------------------------
__global__ void prep_const_all(const float* __restrict__ w0, const float* __restrict__ w1,
                               const float* __restrict__ w2, const float* __restrict__ w3,
                               const float* __restrict__ w4, const float* __restrict__ w5,
                               const float* __restrict__ w6, const float* __restrict__ w7,
                               const float* __restrict__ b11, const float* __restrict__ b12,
                               const float* __restrict__ b21, const float* __restrict__ b22,
                               const float* __restrict__ b31, const float* __restrict__ b32) {
    int b = blockIdx.x;
    if (b >= 574) {
        int pred = b - 574, j = threadIdx.x;
        const float *b1, *W2, *b2; int D, off;
        if (pred == 0)      { b1 = b11; W2 = w1; b2 = b12; D = 64;  off = 0;   }
        else if (pred == 1) { b1 = b21; W2 = w3; b2 = b22; D = 128; off = 64;  }
        else                { b1 = b31; W2 = w5; b2 = b32; D = 192; off = 192; }
        if (j < D) {
            float s = 0.f;
            for (int k = 0; k < D; k++) s = fmaf(fmaxf(b1[k], 0.f), W2[k * D + j], s);
            g_const[off + j] = s + b2[j];
        }
        return;
    }
    const float* W; int K, N, oh, ol, b0;
    if      (b < 18)  { W = w0; K = 64;  N = 64;  oh = 0;      ol = 4608;   b0 = 0;   }
    else if (b < 36)  { W = w1; K = 64;  N = 64;  oh = 9216;   ol = 13824;  b0 = 18;  }
    else if (b < 104) { W = w2; K = 128; N = 128; oh = 18432;  ol = 35840;  b0 = 36;  }
    else if (b < 172) { W = w3; K = 128; N = 128; oh = 53248;  ol = 70656;  b0 = 104; }
    else if (b < 322) { W = w4; K = 192; N = 192; oh = 88064;  ol = 126464; b0 = 172; }
    else if (b < 472) { W = w5; K = 192; N = 192; oh = 164864; ol = 203264; b0 = 322; }
    else if (b < 540) { W = w6; K = 128; N = 128; oh = 241664; ol = 259072; b0 = 472; }
    else              { W = w7; K = 128; N = 64;  oh = 276480; ol = 285184; b0 = 540; }
    int i = (b - b0) * 256 + threadIdx.x;
    int KP = K + 8;
    if (i >= N * KP) return;
    int n = i / KP, k = i - n * KP;
    u16 hv = 0, lv = 0;
    if (k < K) {
        float v = W[k * N + n];
        __nv_bfloat16 h = __float2bfloat16(v);
        __nv_bfloat16 l = __float2bfloat16(v - __bfloat162float(h));
        hv = *reinterpret_cast<u16*>(&h);
        lv = *reinterpret_cast<u16*>(&l);
    }
    g_wbuf[oh + i] = hv;
    g_wbuf[ol + i] = lv;
}

__global__ void deg_all_kernel(const int* __restrict__ ei1, int n1,
                               const int* __restrict__ ei2, int n2,
                               const int* __restrict__ ei3, int n3) {
    int s = blockIdx.y;
    int i = blockIdx.x * 256 + threadIdx.x;
    const int* e; int n, row;
    if (s == 0)     { e = ei1; n = n1; row = 0; }
    else if (s < 3) { e = ei2; n = n2; row = s - 1; }
    else            { e = ei3; n = n3; row = s - 3; }
    if (i < n) atomicAdd(&g_deg[s * MAX_OBJ + e[row * n + i]], 1);
}

// ---------------------------------------------------------------------------
// fused predicate kernel: single-plane A AND B (1-pass GEMMs). ROWS=128 for
// all predicates now (4Mx4N); BOTH selects up-front vs overlapped W2 staging.
// ---------------------------------------------------------------------------
template<int R, int ROWS, int MAXB, bool BOTH>
__global__ void __launch_bounds__(512, MAXB)
pred_mma_kernel(const int* __restrict__ ei, int nAtoms,
                const u16* __restrict__ W1h, const u16* __restrict__ W2h,
                const float* __restrict__ b1, const float* __restrict__ b2) {
    constexpr int D   = 64 * R;
    constexpr int KP  = D + 8;
    constexpr int NG  = 16 / (ROWS / 32);
    constexpr int NPW = D / NG;
    constexpr int NTW = NPW / 8;
    constexpr int TPA = 512 / ROWS;
    constexpr int U4  = 8 / TPA;
    constexpr int WB  = D * KP * 2;        // bytes per weight plane
    constexpr int XB  = ROWS * KP * 2;     // one X plane; region is 2*XB (X + F)
    constexpr int FP  = D + 4;
    constexpr int NWB = BOTH ? 2 : 1;

    extern __shared__ char sm[];
    const u32 su = s2u(sm);
    const u32 W1H = su;
    const u32 W2H = BOTH ? su + WB : su;
    const u32 XHa = su + NWB * WB;
    char* xh_c = sm + NWB * WB;
    float* b1s = (float*)(sm + NWB * WB + 2 * XB);
    float* b2s = b1s + D;
    int*   es  = (int*)(b2s + D);
    float* F   = (float*)(sm + NWB * WB);   // overlays X region (2*XB >= F)

    const int tid = threadIdx.x, warp = tid >> 5, lane = tid & 31;
    const int ng = warp % NG, mg = warp / NG;
    const int base = blockIdx.x * ROWS;

    for (int i = tid * 16; i < WB; i += 512 * 16) {
        CPA16(W1H + i, (const char*)W1h + i);
        if (BOTH) CPA16(W2H + i, (const char*)W2h + i);
    }
    for (int i = tid; i < D; i += 512) { b1s[i] = b1[i]; b2s[i] = b2[i]; }
    for (int i = tid; i < R * ROWS; i += 512) {
        int s = i / ROWS, a = i % ROWS;
        int ga = base + a;
        es[i] = (ga < nAtoms) ? ei[s * nAtoms + ga] : 0;
    }
    __syncthreads();   // es visible

    {   // gather hi plane only
        int a = tid / TPA, h = tid % TPA;
        #pragma unroll
        for (int s = 0; s < R; s++) {
            size_t rb = (size_t)es[s * ROWS + a] * 8 + h * U4;
            u32 bo = (u32)(a * KP + s * 64 + h * (64 / TPA)) * 2;
            #pragma unroll
            for (int q = 0; q < U4; q++)
                CPA16(XHa + bo + q * 16, (const uint4*)g_objh + rb + q);
        }
    }
    CPA_WAIT_ALL();
    __syncthreads();

    float acc[2 * NTW * 4];
    #pragma unroll
    for (int i = 0; i < 2 * NTW * 4; i++) acc[i] = 0.f;
    warp_gemm1<D, D, NG>(XHa, W1H, mg, ng, lane, acc);
    __syncthreads();

    if (!BOTH) {
        for (int i = tid * 16; i < WB; i += 512 * 16)
            CPA16(W2H + i, (const char*)W2h + i);
    }
    // epilogue1: H = relu(C + b1) -> hi plane only
    #pragma unroll
    for (int mtl = 0; mtl < 2; mtl++)
        #pragma unroll
        for (int nt = 0; nt < NTW; nt++) {
            float* d = acc + (mtl * NTW + nt) * 4;
            int row = mg * 32 + mtl * 16 + (lane >> 2);
            int col = ng * NPW + nt * 8 + 2 * (lane & 3);
            float x0 = fmaxf(d[0] + b1s[col], 0.f), x1 = fmaxf(d[1] + b1s[col + 1], 0.f);
            *(u32*)(xh_c + (row * KP + col) * 2) = pack_bf2(x0, x1);
            float x2 = fmaxf(d[2] + b1s[col], 0.f), x3 = fmaxf(d[3] + b1s[col + 1], 0.f);
            *(u32*)(xh_c + ((row + 8) * KP + col) * 2) = pack_bf2(x2, x3);
        }
    if (!BOTH) CPA_WAIT_ALL();
    __syncthreads();

    #pragma unroll
    for (int i = 0; i < 2 * NTW * 4; i++) acc[i] = 0.f;
    warp_gemm1<D, D, NG>(XHa, W2H, mg, ng, lane, acc);
    __syncthreads();

    // epilogue2: C + b2 -> F
    #pragma unroll
    for (int mtl = 0; mtl < 2; mtl++)
        #pragma unroll
        for (int nt = 0; nt < NTW; nt++) {
            float* d = acc + (mtl * NTW + nt) * 4;
            int row = mg * 32 + mtl * 16 + (lane >> 2);
            int col = ng * NPW + nt * 8 + 2 * (lane & 3);
            *(float2*)(F + row * FP + col) =
                make_float2(d[0] + b2s[col], d[1] + b2s[col + 1]);
            *(float2*)(F + (row + 8) * FP + col) =
                make_float2(d[2] + b2s[col], d[3] + b2s[col + 1]);
        }
    __syncthreads();

    // scatter
    {
        int a = tid % ROWS, part = tid / ROWS;
        if (base + a < nAtoms) {
            #pragma unroll
            for (int j = part * (D / TPA); j < part * (D / TPA) + D / TPA; j += 4) {
                float* dst = g_agg + (size_t)es[(j >> 6) * ROWS + a] * HID + (j & 63);
                const float* f = F + a * FP + j;
                red4(dst, f[0], f[1], f[2], f[3]);
            }
        }
    }
}

// ---------------------------------------------------------------------------
// object update: 128 objects/block, 512 threads, 4Mx4N, 3-pass (full precision)
// ---------------------------------------------------------------------------
template<bool L1>
__global__ void __launch_bounds__(512, 1)
update_mma_kernel(const u16* __restrict__ U1h, const u16* __restrict__ U1l,
                  const u16* __restrict__ U2h, const u16* __restrict__ U2l,
                  const float* __restrict__ bu1, const float* __restrict__ bu2,
                  int nObj) {
    constexpr int KP  = 136;
    constexpr int WB1 = 128 * KP * 2;
    constexpr int WB2 = 64 * KP * 2;
    constexpr int XB  = 128 * KP * 2;
    constexpr int FP  = 68;

    extern __shared__ char sm[];
    const u32 su = s2u(sm);
    const u32 U1H = su, U1L = su + WB1;
    const u32 U2H = su + 2 * WB1, U2L = su + 2 * WB1 + WB2;
    const u32 XHa = su + 2 * WB1 + 2 * WB2, XLa = XHa + XB;
    char* xh_c = sm + 2 * WB1 + 2 * WB2;
    char* xl_c = xh_c + XB;
    float* b1s = (float*)(xh_c + 2 * XB);
    float* b2s = b1s + 128;
    float* cs  = b2s + 64;
    float* F   = (float*)xh_c;

    const int tid = threadIdx.x, warp = tid >> 5, lane = tid & 31;
    const int ng = warp & 3, mg = warp >> 2;
    const int base = blockIdx.x * 128;

    for (int i = tid * 16; i < WB1; i += 512 * 16) {
        CPA16(U1H + i, (const char*)U1h + i);
        CPA16(U1L + i, (const char*)U1l + i);
    }
    for (int i = tid * 16; i < WB2; i += 512 * 16) {
        CPA16(U2H + i, (const char*)U2h + i);
        CPA16(U2L + i, (const char*)U2l + i);
    }
    if (tid < 128) b1s[tid] = bu1[tid];
    else if (tid < 192) b2s[tid - 128] = bu2[tid - 128];
    if (L1) { for (int i = tid; i < 384; i += 512) cs[i] = g_const[i]; }
    if (L1) __syncthreads();

    {   // gather cat(obj, agg): 4 threads per object
        int a = tid >> 2, h = tid & 3;
        int go = base + a;
        int gc = (go < nObj) ? go : 0;
        if (h < 2) {
            u32 bo = (u32)(a * KP + h * 32) * 2;
            if (L1) {
                uint4 z = make_uint4(0, 0, 0, 0);
                #pragma unroll
                for (int q = 0; q < 4; q++) {
                    *(uint4*)(xh_c + bo + q * 16) = z;
                    *(uint4*)(xl_c + bo + q * 16) = z;
                }
            } else {
                size_t rb = (size_t)gc * 8 + h * 4;
                #pragma unroll
                for (int q = 0; q < 4; q++) {
                    CPA16(XHa + bo + q * 16, (const uint4*)g_objh + rb + q);
                    CPA16(XLa + bo + q * 16, (const uint4*)g_objl + rb + q);
                }
            }
        } else {
            int hh = h - 2;
            u32 bo = (u32)(a * KP + 64 + hh * 32) * 2;
            if (L1) {
                float degf[6];
                #pragma unroll
                for (int s = 0; s < 6; s++)
                    degf[s] = (float)g_deg[s * MAX_OBJ + gc];
                #pragma unroll
                for (int q = 0; q < 8; q++) {
                    float v[4];
                    #pragma unroll
                    for (int t = 0; t < 4; t++) {
                        int cc = hh * 32 + q * 4 + t;
                        float s = 0.f;
                        #pragma unroll
                        for (int p = 0; p < 6; p++) s = fmaf(degf[p], cs[p * 64 + cc], s);
                        v[t] = s;
                    }
                    u32 h0, l0, h1, l1;
                    split2(v[0], v[1], h0, l0);
                    split2(v[2], v[3], h1, l1);
                    *(u64*)(xh_c + bo + q * 8) = (u64)h0 | ((u64)h1 << 32);
                    *(u64*)(xl_c + bo + q * 8) = (u64)l0 | ((u64)l1 << 32);
                }
            } else {
                const float* src = g_agg + (size_t)gc * HID + hh * 32;
                #pragma unroll
                for (int q = 0; q < 8; q++) {
                    float4 v = *(const float4*)(src + q * 4);
                    u32 h0, l0, h1, l1;
                    split2(v.x, v.y, h0, l0);
                    split2(v.z, v.w, h1, l1);
                    *(u64*)(xh_c + bo + q * 8) = (u64)h0 | ((u64)h1 << 32);
                    *(u64*)(xl_c + bo + q * 8) = (u64)l0 | ((u64)l1 << 32);
                }
            }
            // zero g_agg for next layer (owner row, after read)
            if (!L1 && go < nObj) {
                float4 z4 = make_float4(0.f, 0.f, 0.f, 0.f);
                float* dst = g_agg + (size_t)go * HID + hh * 32;
                #pragma unroll
                for (int q = 0; q < 8; q++) *(float4*)(dst + q * 4) = z4;
            }
        }
    }
    CPA_WAIT_ALL();
    __syncthreads();

    float acc[2 * 4 * 4];
    #pragma unroll
    for (int i = 0; i < 32; i++) acc[i] = 0.f;
    warp_gemm3<128, 128, 4>(XHa, XLa, U1H, U1L, mg, ng, lane, acc);
    __syncthreads();

    // epilogue1 -> H (both planes)
    #pragma unroll
    for (int mtl = 0; mtl < 2; mtl++)
        #pragma unroll
        for (int nt = 0; nt < 4; nt++) {
            float* d = acc + (mtl * 4 + nt) * 4;
            int row = mg * 32 + mtl * 16 + (lane >> 2);
            int col = ng * 32 + nt * 8 + 2 * (lane & 3);
            u32 hh, ll;
            float x0 = fmaxf(d[0] + b1s[col], 0.f), x1 = fmaxf(d[1] + b1s[col + 1], 0.f);
            split2(x0, x1, hh, ll);
            *(u32*)(xh_c + (row * KP + col) * 2) = hh;
            *(u32*)(xl_c + (row * KP + col) * 2) = ll;
            float x2 = fmaxf(d[2] + b1s[col], 0.f), x3 = fmaxf(d[3] + b1s[col + 1], 0.f);
            split2(x2, x3, hh, ll);
            *(u32*)(xh_c + ((row + 8) * KP + col) * 2) = hh;
            *(u32*)(xl_c + ((row + 8) * KP + col) * 2) = ll;
        }
    __syncthreads();

    #pragma unroll
    for (int i = 0; i < 16; i++) acc[i] = 0.f;
    warp_gemm3<128, 64, 4>(XHa, XLa, U2H, U2L, mg, ng, lane, acc);
    __syncthreads();

    // epilogue2 -> F (f32 [128][68])
    #pragma unroll
    for (int mtl = 0; mtl < 2; mtl++)
        #pragma unroll
        for (int nt = 0; nt < 2; nt++) {
            float* d = acc + (mtl * 2 + nt) * 4;
            int row = mg * 32 + mtl * 16 + (lane >> 2);
            int col = ng * 16 + nt * 8 + 2 * (lane & 3);
            *(float2*)(F + row * FP + col) =
                make_float2(d[0] + b2s[col], d[1] + b2s[col + 1]);
            *(float2*)(F + (row + 8) * FP + col) =
                make_float2(d[2] + b2s[col], d[3] + b2s[col + 1]);
        }
    __syncthreads();

    {   // write back: 4 threads/object, 16 cols each
        int a = tid >> 2, h = tid & 3;
        int go = base + a;
        if (go < nObj) {
            const float* f = F + a * FP + h * 16;
            float* dst = g_obj + (size_t)go * HID + h * 16;
            uint4 ph[2], pl[2];
            u32* phu = (u32*)ph; u32* plu = (u32*)pl;
            #pragma unroll
            for (int q = 0; q < 4; q++) {
                float4 v = *(const float4*)(f + q * 4);
                *(float4*)(dst + q * 4) = v;
                split2(v.x, v.y, phu[q * 2], plu[q * 2]);
                split2(v.z, v.w, phu[q * 2 + 1], plu[q * 2 + 1]);
            }
            uint4* dh = (uint4*)g_objh + (size_t)go * 8 + h * 2;
            uint4* dl = (uint4*)g_objl + (size_t)go * 8 + h * 2;
            dh[0] = ph[0]; dh[1] = ph[1];
            dl[0] = pl[0]; dl[1] = pl[1];
        }
    }
}

// ---------------------------------------------------------------------------
// small kernels
// ---------------------------------------------------------------------------
__global__ void zero_init_kernel(int nObj) {
    int i = blockIdx.x * 256 + threadIdx.x;
    if (i < 6 * MAX_OBJ)      g_deg[i] = 0;
    if (i < MAX_GRAPHS * HID) g_pooled[i] = 0.f;
    if (i < nObj * HID)       g_agg[i] = 0.f;
}
__global__ void pool_kernel(const int* __restrict__ batch, int nObj) {
    int c = threadIdx.x;
    int base = blockIdx.x * 64;
    int end = min(base + 64, nObj);
    int cur = -1; float s = 0.f;
    for (int o = base; o < end; o++) {
        int b = batch[o];
        if (b != cur) {
            if (cur >= 0) atomicAdd(&g_pooled[cur * HID + c], s);
            cur = b; s = 0.f;
        }
        s += g_obj[(size_t)o * HID + c];
    }
    if (cur >= 0) atomicAdd(&g_pooled[cur * HID + c], s);
}
__global__ void readout_kernel(const float* __restrict__ w1, const float* __restrict__ b1,
                               const float* __restrict__ w2, const float* __restrict__ b2,
                               float* __restrict__ out) {
    __shared__ float p[64];
    __shared__ float red[4];
    int g = blockIdx.x, t = threadIdx.x;
    if (t < 64) p[t] = g_pooled[g * HID + t];
    __syncthreads();
    float acc = 0.f;
    #pragma unroll
    for (int k = 0; k < 64; k++) acc = fmaf(p[k], w1[k * 128 + t], acc);
    acc = fmaxf(acc + b1[t], 0.f) * w2[t];
    #pragma unroll
    for (int off = 16; off; off >>= 1) acc += __shfl_down_sync(0xffffffffu, acc, off);
    if ((t & 31) == 0) red[t >> 5] = acc;
    __syncthreads();
    if (t == 0) out[g] = red[0] + red[1] + red[2] + red[3] + b2[0];
}

// ---------------------------------------------------------------------------
extern "C" void kernel_launch(void* const* d_in, const int* in_sizes, int n_in,
                              void* d_out, int out_size) {
    const float* w_p1_1 = (const float*)d_in[4];
    const float* b_p1_1 = (const float*)d_in[5];
    const float* w_p1_2 = (const float*)d_in[6];
    const float* b_p1_2 = (const float*)d_in[7];
    const float* w_p2_1 = (const float*)d_in[8];
    const float* b_p2_1 = (const float*)d_in[9];
    const float* w_p2_2 = (const float*)d_in[10];
    const float* b_p2_2 = (const float*)d_in[11];
    const float* w_p3_1 = (const float*)d_in[12];
    const float* b_p3_1 = (const float*)d_in[13];
    const float* w_p3_2 = (const float*)d_in[14];
    const float* b_p3_2 = (const float*)d_in[15];
    const float* w_u1   = (const float*)d_in[16];
    const float* b_u1   = (const float*)d_in[17];
    const float* w_u2   = (const float*)d_in[18];
    const float* b_u2   = (const float*)d_in[19];
    const float* w_r1   = (const float*)d_in[20];
    const float* b_r1   = (const float*)d_in[21];
    const float* w_r2   = (const float*)d_in[22];
    const float* b_r2   = (const float*)d_in[23];
    const int*   ei_p1  = (const int*)d_in[24];
    const int*   ei_p2  = (const int*)d_in[25];
    const int*   ei_p3  = (const int*)d_in[26];
    const int*   batch  = (const int*)d_in[27];

    const int nObj = in_sizes[0];
    const int nP1  = in_sizes[24];
    const int nP2  = in_sizes[25] / 2;
    const int nP3  = in_sizes[26] / 3;
    const int nGraphs = out_size;
    float* out = (float*)d_out;

    u16* wb = nullptr;
    cudaGetSymbolAddress((void**)&wb, g_wbuf);

    // smem: NWB*WB + 2*XB (X + F region) + biases + es
    const int smem1 = 2 * (64 * 72 * 2)   + 2 * (128 * 72 * 2)  + 8 * 64  + 1 * 128 * 4;
    const int smem2 = 2 * (128 * 136 * 2) + 2 * (128 * 136 * 2) + 8 * 128 + 2 * 128 * 4;
    const int smem3 = 1 * (192 * 200 * 2) + 2 * (128 * 200 * 2) + 8 * 192 + 3 * 128 * 4;
    const int smemU = 2 * (128 * 136 * 2) + 2 * (64 * 136 * 2)
                    + 2 * (128 * 136 * 2) + 128 * 4 + 64 * 4 + 384 * 4;
    cudaFuncSetAttribute((pred_mma_kernel<1, 128, 2, true>), cudaFuncAttributeMaxDynamicSharedMemorySize, smem1);
    cudaFuncSetAttribute((pred_mma_kernel<2, 128, 1, true>), cudaFuncAttributeMaxDynamicSharedMemorySize, smem2);
    cudaFuncSetAttribute((pred_mma_kernel<3, 128, 1, false>), cudaFuncAttributeMaxDynamicSharedMemorySize, smem3);
    cudaFuncSetAttribute(update_mma_kernel<true>, cudaFuncAttributeMaxDynamicSharedMemorySize, smemU);
    cudaFuncSetAttribute(update_mma_kernel<false>, cudaFuncAttributeMaxDynamicSharedMemorySize, smemU);

    const int bObj = (nObj + 127) / 128;
    const int bP1  = (nP1 + 127) / 128;
    const int bP2  = (nP2 + 127) / 128;
    const int bP3  = (nP3 + 127) / 128;
    int nmax = nP1 > nP2 ? nP1 : nP2; if (nP3 > nmax) nmax = nP3;

    int zn = nObj * HID; if (6 * MAX_OBJ > zn) zn = 6 * MAX_OBJ;
    zero_init_kernel<<<(zn + 255) / 256, 256>>>(nObj);                        // 0
    prep_const_all<<<577, 256>>>(w_p1_1, w_p1_2, w_p2_1, w_p2_2,              // 1
                                 w_p3_1, w_p3_2, w_u1, w_u2,
                                 b_p1_1, b_p1_2, b_p2_1, b_p2_2, b_p3_1, b_p3_2);
    deg_all_kernel<<<dim3((nmax + 255) / 256, 6), 256>>>(ei_p1, nP1,          // 2
                                                         ei_p2, nP2,
                                                         ei_p3, nP3);
    update_mma_kernel<true><<<bObj, 512, smemU>>>(wb + 241664, wb + 259072,   // 3
                                                  wb + 276480, wb + 285184,
                                                  b_u1, b_u2, nObj);

    const bool fork = g_hx.ok;
    cudaStream_t sA = fork ? g_hx.s1 : (cudaStream_t)0;
    cudaStream_t sB = fork ? g_hx.s2 : (cudaStream_t)0;

    for (int layer = 1; layer < 3; layer++) {
        if (fork) {
            cudaEventRecord(g_hx.evA, 0);
            cudaStreamWaitEvent(sA, g_hx.evA, 0);
            cudaStreamWaitEvent(sB, g_hx.evA, 0);
        }
        pred_mma_kernel<1, 128, 2, true><<<bP1, 512, smem1, sA>>>(
            ei_p1, nP1, wb + 0, wb + 9216, b_p1_1, b_p1_2);
        pred_mma_kernel<2, 128, 1, true><<<bP2, 512, smem2, sB>>>(
            ei_p2, nP2, wb + 18432, wb + 53248, b_p2_1, b_p2_2);
        pred_mma_kernel<3, 128, 1, false><<<bP3, 512, smem3>>>(
            ei_p3, nP3, wb + 88064, wb + 164864, b_p3_1, b_p3_2);
        if (fork) {
            cudaEventRecord(g_hx.ev1, sA);
            cudaEventRecord(g_hx.ev2, sB);
            cudaStreamWaitEvent((cudaStream_t)0, g_hx.ev1, 0);
            cudaStreamWaitEvent((cudaStream_t)0, g_hx.ev2, 0);
        }
        update_mma_kernel<false><<<bObj, 512, smemU>>>(wb + 241664, wb + 259072,
                                                       wb + 276480, wb + 285184,
                                                       b_u1, b_u2, nObj);
    }

    pool_kernel<<<(nObj + 63) / 64, 64>>>(batch, nObj);
    readout_kernel<<<nGraphs, 128>>>(w_r1, b_r1, w_r2, b_r2, out);
}